// round 4
// baseline (speedup 1.0000x reference)
#include <cuda_runtime.h>
#include <mma.h>
using namespace nvcuda;

#define NB  8
#define SLD 1024
#define SLM 1024
#define DD  1024
#define HH  16
#define HS  64

// Scratch for attention context, [N, LD, D] layout (32 MB)
__device__ float g_ctx[(size_t)NB * SLD * DD];

__device__ __forceinline__ void mma_tf32(float c[4], const unsigned a[4], const unsigned b[2]) {
    asm volatile(
        "mma.sync.aligned.m16n8k8.row.col.f32.tf32.tf32.f32 "
        "{%0,%1,%2,%3}, {%4,%5,%6,%7}, {%8,%9}, {%0,%1,%2,%3};\n"
        : "+f"(c[0]), "+f"(c[1]), "+f"(c[2]), "+f"(c[3])
        : "r"(a[0]), "r"(a[1]), "r"(a[2]), "r"(a[3]), "r"(b[0]), "r"(b[1]));
}

__device__ __forceinline__ void cp16(unsigned saddr, const float* gptr) {
    asm volatile("cp.async.cg.shared.global [%0], [%1], 16;\n" :: "r"(saddr), "l"(gptr));
}

__device__ __forceinline__ unsigned f2tf(float x) {
    unsigned u;
    asm("cvt.rna.tf32.f32 %0, %1;" : "=r"(u) : "f"(x));
    return u;
}

// ==================== fused flash-style attention ====================
#define BQ 64
#define BK 64
#define AT 256
#define LDK 68

#define OFF_K0   0
#define OFF_K1   (64*LDK)
#define OFF_P    (2*64*LDK)
#define OFF_Q    (3*64*LDK)
#define OFF_M    (4*64*LDK)
#define OFF_RED  (OFF_M + 1024)
#define ATT_SMEM_FLOATS (OFF_RED + 64*4)   // 18688 floats = 74752 B

__global__ __launch_bounds__(AT, 3)
void attn_kernel(const float* __restrict__ inp,
                 const float* __restrict__ mem,
                 const float* __restrict__ maskp)
{
    extern __shared__ float sm[];
    const unsigned sbase = (unsigned)__cvta_generic_to_shared(sm);

    const int tid  = threadIdx.x;
    const int lane = tid & 31;
    const int warp = tid >> 5;
    const int g = lane >> 2;
    const int q = lane & 3;
    const int wm = warp >> 2;      // 0..1
    const int wn = warp & 3;       // 0..3
    const int qt = blockIdx.x, h = blockIdx.y, b = blockIdx.z;

    const float* kbase = mem + (size_t)b * SLM * DD + h * HS;

    auto cpK = [&](int kt, int buf) {
        const int base = buf ? OFF_K1 : OFF_K0;
        #pragma unroll
        for (int t = 0; t < 4; t++) {
            int idx = tid + t * AT;
            int r = idx >> 4, c4 = idx & 15;
            unsigned sa = sbase + (unsigned)(base + r * LDK + c4 * 4) * 4u;
            cp16(sa, kbase + (size_t)(kt * BK + r) * DD + c4 * 4);
        }
        asm volatile("cp.async.commit_group;\n" ::: "memory");
    };
    cpK(0, 0);

    const float* qbase = inp + ((size_t)(b * SLD + qt * BQ)) * DD + h * HS;
    #pragma unroll
    for (int t = 0; t < 4; t++) {
        int idx = tid + t * AT;
        int r = idx >> 4, c4 = idx & 15;
        float4 v = *(const float4*)(qbase + (size_t)r * DD + c4 * 4);
        v.x = wmma::__float_to_tf32(v.x); v.y = wmma::__float_to_tf32(v.y);
        v.z = wmma::__float_to_tf32(v.z); v.w = wmma::__float_to_tf32(v.w);
        *(float4*)&sm[OFF_Q + r * LDK + c4 * 4] = v;
    }
    for (int i = tid; i < SLM; i += AT)
        sm[OFF_M + i] = -1e30f * (1.0f - maskp[(size_t)b * SLM + i]);

    float oc[2][2][4] = {};
    float lpart[4] = {0.f, 0.f, 0.f, 0.f};
    int buf = 0;

    for (int kt = 0; kt < SLM / BK; kt++) {
        asm volatile("cp.async.wait_group 0;\n" ::: "memory");
        __syncthreads();
        if (kt + 1 < SLM / BK) cpK(kt + 1, buf ^ 1);

        const float* sK = sm + (buf ? OFF_K1 : OFF_K0);

        float sc[2][2][4] = {};
        #pragma unroll
        for (int kk = 0; kk < 8; kk++) {
            unsigned a[2][4], bb[2][2];
            #pragma unroll
            for (int mf = 0; mf < 2; mf++) {
                const float* qp = sm + OFF_Q + kk * 8 + q;
                int r0 = wm * 32 + mf * 16;
                a[mf][0] = __float_as_uint(qp[(r0 + g) * LDK]);
                a[mf][1] = __float_as_uint(qp[(r0 + g + 8) * LDK]);
                a[mf][2] = __float_as_uint(qp[(r0 + g) * LDK + 4]);
                a[mf][3] = __float_as_uint(qp[(r0 + g + 8) * LDK + 4]);
            }
            #pragma unroll
            for (int nf = 0; nf < 2; nf++) {
                int n0 = wn * 16 + nf * 8;
                bb[nf][0] = __float_as_uint(sK[(n0 + g) * LDK + kk * 8 + q]);
                bb[nf][1] = __float_as_uint(sK[(n0 + g) * LDK + kk * 8 + q + 4]);
            }
            #pragma unroll
            for (int mf = 0; mf < 2; mf++)
                #pragma unroll
                for (int nf = 0; nf < 2; nf++)
                    mma_tf32(sc[mf][nf], a[mf], bb[nf]);
        }

        #pragma unroll
        for (int mf = 0; mf < 2; mf++) {
            int row = wm * 32 + mf * 16;
            #pragma unroll
            for (int nf = 0; nf < 2; nf++) {
                int col = wn * 16 + nf * 8 + 2 * q;
                float m0v = sm[OFF_M + kt * 64 + col];
                float m1v = sm[OFF_M + kt * 64 + col + 1];
                float p0 = __expf(sc[mf][nf][0] * 0.125f + m0v);
                float p1 = __expf(sc[mf][nf][1] * 0.125f + m1v);
                float p2 = __expf(sc[mf][nf][2] * 0.125f + m0v);
                float p3 = __expf(sc[mf][nf][3] * 0.125f + m1v);
                lpart[mf * 2 + 0] += p0 + p1;
                lpart[mf * 2 + 1] += p2 + p3;
                *(float2*)&sm[OFF_P + (row + g) * LDK + col]     = make_float2(p0, p1);
                *(float2*)&sm[OFF_P + (row + g + 8) * LDK + col] = make_float2(p2, p3);
            }
        }
        __syncthreads();

        #pragma unroll
        for (int kk = 0; kk < 8; kk++) {
            unsigned a[2][4], bb[2][2];
            #pragma unroll
            for (int mf = 0; mf < 2; mf++) {
                const float* pp = sm + OFF_P + kk * 8 + q;
                int r0 = wm * 32 + mf * 16;
                a[mf][0] = __float_as_uint(pp[(r0 + g) * LDK]);
                a[mf][1] = __float_as_uint(pp[(r0 + g + 8) * LDK]);
                a[mf][2] = __float_as_uint(pp[(r0 + g) * LDK + 4]);
                a[mf][3] = __float_as_uint(pp[(r0 + g + 8) * LDK + 4]);
            }
            #pragma unroll
            for (int nf = 0; nf < 2; nf++) {
                int n0 = wn * 16 + nf * 8;
                bb[nf][0] = __float_as_uint(sK[(kk * 8 + q) * LDK + n0 + g]);
                bb[nf][1] = __float_as_uint(sK[(kk * 8 + q + 4) * LDK + n0 + g]);
            }
            #pragma unroll
            for (int mf = 0; mf < 2; mf++)
                #pragma unroll
                for (int nf = 0; nf < 2; nf++)
                    mma_tf32(oc[mf][nf], a[mf], bb[nf]);
        }
        buf ^= 1;
    }

    #pragma unroll
    for (int i = 0; i < 4; i++) {
        lpart[i] += __shfl_xor_sync(0xffffffffu, lpart[i], 1);
        lpart[i] += __shfl_xor_sync(0xffffffffu, lpart[i], 2);
    }
    if (q == 0) {
        #pragma unroll
        for (int mf = 0; mf < 2; mf++)
            #pragma unroll
            for (int rg = 0; rg < 2; rg++) {
                int row = wm * 32 + mf * 16 + g + rg * 8;
                sm[OFF_RED + row * 4 + wn] = lpart[mf * 2 + rg];
            }
    }
    __syncthreads();

    float* obase = g_ctx + ((size_t)(b * SLD + qt * BQ)) * DD + h * HS;
    #pragma unroll
    for (int mf = 0; mf < 2; mf++) {
        #pragma unroll
        for (int rg = 0; rg < 2; rg++) {
            int row = wm * 32 + mf * 16 + g + rg * 8;
            float L = sm[OFF_RED + row * 4 + 0] + sm[OFF_RED + row * 4 + 1]
                    + sm[OFF_RED + row * 4 + 2] + sm[OFF_RED + row * 4 + 3];
            float inv = 1.0f / L;
            #pragma unroll
            for (int nf = 0; nf < 2; nf++) {
                float2 v;
                v.x = oc[mf][nf][rg * 2 + 0] * inv;
                v.y = oc[mf][nf][rg * 2 + 1] * inv;
                *(float2*)&obase[(size_t)row * DD + wn * 16 + nf * 8 + 2 * q] = v;
            }
        }
    }
}

// ==================== projection GEMM + gated activation ====================
// out[m][n] = act( sum_k X[m][k] Wc[n][k] + bc[n] ), X = [input | ctx]
// CTA tile 128x128x32, 256 threads, warp grid 2x4, warp tile 64x32.
// cp.async double-buffered; raw mma.m16n8k8 tf32; epilogue direct to global.
#define GBM 128
#define GBN 128
#define GBK 32
#define GLDS 36
#define GT 256

#define GX0 0
#define GW0 (GBM*GLDS)
#define GX1 (GW0 + GBN*GLDS)
#define GW1 (GX1 + GBM*GLDS)
#define GEMM_SMEM_FLOATS (GW1 + GBN*GLDS)   // 18432 floats = 73728 B

__device__ __forceinline__ float gated_act(float o) {
    o = fminf(fmaxf(o, -30.0f), 30.0f);
    float e = __expf(-o);
    return (1.0f - e) / (1.0f + e * e);   // == sigmoid(o)*tanh(o)
}

__global__ __launch_bounds__(GT, 2)
void out_gemm_kernel(const float* __restrict__ inp,
                     const float* __restrict__ Wc,
                     const float* __restrict__ bc,
                     float* __restrict__ outp)
{
    extern __shared__ float sg[];
    const unsigned sbase = (unsigned)__cvta_generic_to_shared(sg);

    const int tid  = threadIdx.x;
    const int lane = tid & 31;
    const int warp = tid >> 5;
    const int g = lane >> 2;
    const int q = lane & 3;
    const int wm = warp >> 2;       // 0..1 -> rows wm*64
    const int wn = warp & 3;        // 0..3 -> cols wn*32
    const int n0 = blockIdx.x * GBN;
    const int m0 = blockIdx.y * GBM;

    // stage K-block kb into buffer buf (X 128x32, W 128x32, raw fp32)
    auto cpBlk = [&](int kb, int buf) {
        const float* src = (kb < DD) ? inp : g_ctx;
        const int koff = kb & (DD - 1);
        const int bx = buf ? GX1 : GX0;
        const int bw = buf ? GW1 : GW0;
        #pragma unroll
        for (int t = 0; t < 4; t++) {
            int idx = tid + t * GT;             // 0..1023
            int r = idx >> 3, c4 = idx & 7;     // row 0..127, float4 col 0..7
            unsigned sa = sbase + (unsigned)(bx + r * GLDS + c4 * 4) * 4u;
            cp16(sa, src + (size_t)(m0 + r) * DD + koff + c4 * 4);
            unsigned sw = sbase + (unsigned)(bw + r * GLDS + c4 * 4) * 4u;
            cp16(sw, Wc + (size_t)(n0 + r) * (2 * DD) + kb + c4 * 4);
        }
        asm volatile("cp.async.commit_group;\n" ::: "memory");
    };
    cpBlk(0, 0);

    float acc[4][4][4] = {};
    int buf = 0;

    for (int kb = 0; kb < 2 * DD; kb += GBK) {
        asm volatile("cp.async.wait_group 0;\n" ::: "memory");
        __syncthreads();
        if (kb + GBK < 2 * DD) cpBlk(kb + GBK, buf ^ 1);

        const float* sX = sg + (buf ? GX1 : GX0);
        const float* sW = sg + (buf ? GW1 : GW0);

        #pragma unroll
        for (int kk = 0; kk < GBK; kk += 8) {
            unsigned a[4][4], bb[4][2];
            #pragma unroll
            for (int mi = 0; mi < 4; mi++) {
                const float* xp = sX + kk + q;
                int r0 = wm * 64 + mi * 16;
                a[mi][0] = f2tf(xp[(r0 + g) * GLDS]);
                a[mi][1] = f2tf(xp[(r0 + g + 8) * GLDS]);
                a[mi][2] = f2tf(xp[(r0 + g) * GLDS + 4]);
                a[mi][3] = f2tf(xp[(r0 + g + 8) * GLDS + 4]);
            }
            #pragma unroll
            for (int ni = 0; ni < 4; ni++) {
                int nw = wn * 32 + ni * 8;
                bb[ni][0] = f2tf(sW[(nw + g) * GLDS + kk + q]);
                bb[ni][1] = f2tf(sW[(nw + g) * GLDS + kk + q + 4]);
            }
            #pragma unroll
            for (int mi = 0; mi < 4; mi++)
                #pragma unroll
                for (int ni = 0; ni < 4; ni++)
                    mma_tf32(acc[mi][ni], a[mi], bb[ni]);
        }
        buf ^= 1;
    }

    // ---- epilogue: bias + sigmoid*tanh, direct to global ----
    #pragma unroll
    for (int ni = 0; ni < 4; ni++) {
        int col = n0 + wn * 32 + ni * 8 + 2 * q;
        float b0 = bc[col], b1 = bc[col + 1];
        #pragma unroll
        for (int mi = 0; mi < 4; mi++) {
            int row = m0 + wm * 64 + mi * 16 + g;
            float2 v0, v1;
            v0.x = gated_act(acc[mi][ni][0] + b0);
            v0.y = gated_act(acc[mi][ni][1] + b1);
            v1.x = gated_act(acc[mi][ni][2] + b0);
            v1.y = gated_act(acc[mi][ni][3] + b1);
            *(float2*)&outp[(size_t)row * DD + col]       = v0;
            *(float2*)&outp[(size_t)(row + 8) * DD + col] = v1;
        }
    }
}

extern "C" void kernel_launch(void* const* d_in, const int* in_sizes, int n_in,
                              void* d_out, int out_size)
{
    const float* inp  = (const float*)d_in[0];   // [8,1024,1024]
    const float* mem  = (const float*)d_in[1];   // [8,1024,1024]
    const float* mask = (const float*)d_in[2];   // [8,1024]
    const float* Wc   = (const float*)d_in[3];   // [1024,2048]
    const float* bc   = (const float*)d_in[4];   // [1024]
    float* outp = (float*)d_out;                 // [8,1024,1024]

    const size_t att_smem = (size_t)ATT_SMEM_FLOATS * sizeof(float);
    cudaFuncSetAttribute(attn_kernel, cudaFuncAttributeMaxDynamicSharedMemorySize,
                         (int)att_smem);
    const size_t gemm_smem = (size_t)GEMM_SMEM_FLOATS * sizeof(float);
    cudaFuncSetAttribute(out_gemm_kernel, cudaFuncAttributeMaxDynamicSharedMemorySize,
                         (int)gemm_smem);

    dim3 agrid(SLD / BQ, HH, NB);              // 16 x 16 x 8 = 2048 blocks
    attn_kernel<<<agrid, AT, att_smem>>>(inp, mem, mask);

    dim3 ggrid(DD / GBN, (NB * SLD) / GBM);    // 8 x 64 = 512 blocks
    out_gemm_kernel<<<ggrid, GT, gemm_smem>>>(inp, Wc, bc, outp);
}

// round 5
// speedup vs baseline: 1.5935x; 1.5935x over previous
#include <cuda_runtime.h>
#include <mma.h>
using namespace nvcuda;

#define NB  8
#define SLD 1024
#define SLM 1024
#define DD  1024
#define HH  16
#define HS  64

// Scratch: attention context (tf32-rounded), rounded input X, rounded Wc
__device__ float g_ctx[(size_t)NB * SLD * DD];        // 32 MB
__device__ float g_xtf[(size_t)NB * SLD * DD];        // 32 MB
__device__ float g_wtf[(size_t)DD * 2 * DD];          // 8 MB

__device__ __forceinline__ void mma_tf32(float c[4], const unsigned a[4], const unsigned b[2]) {
    asm volatile(
        "mma.sync.aligned.m16n8k8.row.col.f32.tf32.tf32.f32 "
        "{%0,%1,%2,%3}, {%4,%5,%6,%7}, {%8,%9}, {%0,%1,%2,%3};\n"
        : "+f"(c[0]), "+f"(c[1]), "+f"(c[2]), "+f"(c[3])
        : "r"(a[0]), "r"(a[1]), "r"(a[2]), "r"(a[3]), "r"(b[0]), "r"(b[1]));
}

__device__ __forceinline__ void cp16(unsigned saddr, const float* gptr) {
    asm volatile("cp.async.cg.shared.global [%0], [%1], 16;\n" :: "r"(saddr), "l"(gptr));
}

__device__ __forceinline__ unsigned f2tf(float x) {
    unsigned u;
    asm("cvt.rna.tf32.f32 %0, %1;" : "=r"(u) : "f"(x));
    return u;
}

// ==================== prep: RN-round to tf32 in memory ====================
__global__ __launch_bounds__(256)
void round_tf32_kernel(const float* __restrict__ src, float* __restrict__ dst, int n4)
{
    int i = blockIdx.x * 256 + threadIdx.x;
    if (i < n4) {
        float4 v = ((const float4*)src)[i];
        v.x = __uint_as_float(f2tf(v.x));
        v.y = __uint_as_float(f2tf(v.y));
        v.z = __uint_as_float(f2tf(v.z));
        v.w = __uint_as_float(f2tf(v.w));
        ((float4*)dst)[i] = v;
    }
}

// ==================== fused flash-style attention ====================
#define BQ 64
#define BK 64
#define AT 256
#define LDK 68

#define OFF_K0   0
#define OFF_K1   (64*LDK)
#define OFF_P    (2*64*LDK)
#define OFF_Q    (3*64*LDK)
#define OFF_M    (4*64*LDK)
#define OFF_RED  (OFF_M + 1024)
#define ATT_SMEM_FLOATS (OFF_RED + 64*4)   // 18688 floats = 74752 B

__global__ __launch_bounds__(AT, 3)
void attn_kernel(const float* __restrict__ inp,
                 const float* __restrict__ mem,
                 const float* __restrict__ maskp)
{
    extern __shared__ float sm[];
    const unsigned sbase = (unsigned)__cvta_generic_to_shared(sm);

    const int tid  = threadIdx.x;
    const int lane = tid & 31;
    const int warp = tid >> 5;
    const int g = lane >> 2;
    const int q = lane & 3;
    const int wm = warp >> 2;      // 0..1
    const int wn = warp & 3;       // 0..3
    const int qt = blockIdx.x, h = blockIdx.y, b = blockIdx.z;

    const float* kbase = mem + (size_t)b * SLM * DD + h * HS;

    auto cpK = [&](int kt, int buf) {
        const int base = buf ? OFF_K1 : OFF_K0;
        #pragma unroll
        for (int t = 0; t < 4; t++) {
            int idx = tid + t * AT;
            int r = idx >> 4, c4 = idx & 15;
            unsigned sa = sbase + (unsigned)(base + r * LDK + c4 * 4) * 4u;
            cp16(sa, kbase + (size_t)(kt * BK + r) * DD + c4 * 4);
        }
        asm volatile("cp.async.commit_group;\n" ::: "memory");
    };
    cpK(0, 0);

    const float* qbase = inp + ((size_t)(b * SLD + qt * BQ)) * DD + h * HS;
    #pragma unroll
    for (int t = 0; t < 4; t++) {
        int idx = tid + t * AT;
        int r = idx >> 4, c4 = idx & 15;
        float4 v = *(const float4*)(qbase + (size_t)r * DD + c4 * 4);
        v.x = __uint_as_float(f2tf(v.x)); v.y = __uint_as_float(f2tf(v.y));
        v.z = __uint_as_float(f2tf(v.z)); v.w = __uint_as_float(f2tf(v.w));
        *(float4*)&sm[OFF_Q + r * LDK + c4 * 4] = v;
    }
    for (int i = tid; i < SLM; i += AT)
        sm[OFF_M + i] = -1e30f * (1.0f - maskp[(size_t)b * SLM + i]);

    float oc[2][2][4] = {};
    float lpart[4] = {0.f, 0.f, 0.f, 0.f};
    int buf = 0;

    for (int kt = 0; kt < SLM / BK; kt++) {
        asm volatile("cp.async.wait_group 0;\n" ::: "memory");
        __syncthreads();
        if (kt + 1 < SLM / BK) cpK(kt + 1, buf ^ 1);

        const float* sK = sm + (buf ? OFF_K1 : OFF_K0);

        float sc[2][2][4] = {};
        #pragma unroll
        for (int kk = 0; kk < 8; kk++) {
            unsigned a[2][4], bb[2][2];
            #pragma unroll
            for (int mf = 0; mf < 2; mf++) {
                const float* qp = sm + OFF_Q + kk * 8 + q;
                int r0 = wm * 32 + mf * 16;
                a[mf][0] = __float_as_uint(qp[(r0 + g) * LDK]);
                a[mf][1] = __float_as_uint(qp[(r0 + g + 8) * LDK]);
                a[mf][2] = __float_as_uint(qp[(r0 + g) * LDK + 4]);
                a[mf][3] = __float_as_uint(qp[(r0 + g + 8) * LDK + 4]);
            }
            #pragma unroll
            for (int nf = 0; nf < 2; nf++) {
                int n0 = wn * 16 + nf * 8;
                bb[nf][0] = __float_as_uint(sK[(n0 + g) * LDK + kk * 8 + q]);
                bb[nf][1] = __float_as_uint(sK[(n0 + g) * LDK + kk * 8 + q + 4]);
            }
            #pragma unroll
            for (int mf = 0; mf < 2; mf++)
                #pragma unroll
                for (int nf = 0; nf < 2; nf++)
                    mma_tf32(sc[mf][nf], a[mf], bb[nf]);
        }

        #pragma unroll
        for (int mf = 0; mf < 2; mf++) {
            int row = wm * 32 + mf * 16;
            #pragma unroll
            for (int nf = 0; nf < 2; nf++) {
                int col = wn * 16 + nf * 8 + 2 * q;
                float m0v = sm[OFF_M + kt * 64 + col];
                float m1v = sm[OFF_M + kt * 64 + col + 1];
                float p0 = __expf(sc[mf][nf][0] * 0.125f + m0v);
                float p1 = __expf(sc[mf][nf][1] * 0.125f + m1v);
                float p2 = __expf(sc[mf][nf][2] * 0.125f + m0v);
                float p3 = __expf(sc[mf][nf][3] * 0.125f + m1v);
                lpart[mf * 2 + 0] += p0 + p1;
                lpart[mf * 2 + 1] += p2 + p3;
                *(float2*)&sm[OFF_P + (row + g) * LDK + col]     = make_float2(p0, p1);
                *(float2*)&sm[OFF_P + (row + g + 8) * LDK + col] = make_float2(p2, p3);
            }
        }
        __syncthreads();

        #pragma unroll
        for (int kk = 0; kk < 8; kk++) {
            unsigned a[2][4], bb[2][2];
            #pragma unroll
            for (int mf = 0; mf < 2; mf++) {
                const float* pp = sm + OFF_P + kk * 8 + q;
                int r0 = wm * 32 + mf * 16;
                a[mf][0] = __float_as_uint(pp[(r0 + g) * LDK]);
                a[mf][1] = __float_as_uint(pp[(r0 + g + 8) * LDK]);
                a[mf][2] = __float_as_uint(pp[(r0 + g) * LDK + 4]);
                a[mf][3] = __float_as_uint(pp[(r0 + g + 8) * LDK + 4]);
            }
            #pragma unroll
            for (int nf = 0; nf < 2; nf++) {
                int n0 = wn * 16 + nf * 8;
                bb[nf][0] = __float_as_uint(sK[(kk * 8 + q) * LDK + n0 + g]);
                bb[nf][1] = __float_as_uint(sK[(kk * 8 + q + 4) * LDK + n0 + g]);
            }
            #pragma unroll
            for (int mf = 0; mf < 2; mf++)
                #pragma unroll
                for (int nf = 0; nf < 2; nf++)
                    mma_tf32(oc[mf][nf], a[mf], bb[nf]);
        }
        buf ^= 1;
    }

    #pragma unroll
    for (int i = 0; i < 4; i++) {
        lpart[i] += __shfl_xor_sync(0xffffffffu, lpart[i], 1);
        lpart[i] += __shfl_xor_sync(0xffffffffu, lpart[i], 2);
    }
    if (q == 0) {
        #pragma unroll
        for (int mf = 0; mf < 2; mf++)
            #pragma unroll
            for (int rg = 0; rg < 2; rg++) {
                int row = wm * 32 + mf * 16 + g + rg * 8;
                sm[OFF_RED + row * 4 + wn] = lpart[mf * 2 + rg];
            }
    }
    __syncthreads();

    // ---- normalize, RN-round to tf32, write context ----
    float* obase = g_ctx + ((size_t)(b * SLD + qt * BQ)) * DD + h * HS;
    #pragma unroll
    for (int mf = 0; mf < 2; mf++) {
        #pragma unroll
        for (int rg = 0; rg < 2; rg++) {
            int row = wm * 32 + mf * 16 + g + rg * 8;
            float L = sm[OFF_RED + row * 4 + 0] + sm[OFF_RED + row * 4 + 1]
                    + sm[OFF_RED + row * 4 + 2] + sm[OFF_RED + row * 4 + 3];
            float inv = 1.0f / L;
            #pragma unroll
            for (int nf = 0; nf < 2; nf++) {
                float2 v;
                v.x = __uint_as_float(f2tf(oc[mf][nf][rg * 2 + 0] * inv));
                v.y = __uint_as_float(f2tf(oc[mf][nf][rg * 2 + 1] * inv));
                *(float2*)&obase[(size_t)row * DD + wn * 16 + nf * 8 + 2 * q] = v;
            }
        }
    }
}

// ==================== projection GEMM + gated activation ====================
// Operands pre-rounded to tf32 in memory -> inner loop is pure LDS + HMMA.
#define GBM 128
#define GBN 128
#define GBK 32
#define GLDS 36
#define GT 256

#define GX0 0
#define GW0 (GBM*GLDS)
#define GX1 (GW0 + GBN*GLDS)
#define GW1 (GX1 + GBM*GLDS)
#define GEMM_SMEM_FLOATS (GW1 + GBN*GLDS)   // 18432 floats = 73728 B

__device__ __forceinline__ float gated_act(float o) {
    o = fminf(fmaxf(o, -30.0f), 30.0f);
    float e = __expf(-o);
    return (1.0f - e) / (1.0f + e * e);   // == sigmoid(o)*tanh(o)
}

__global__ __launch_bounds__(GT, 2)
void out_gemm_kernel(const float* __restrict__ bc,
                     float* __restrict__ outp)
{
    extern __shared__ float sg[];
    const unsigned sbase = (unsigned)__cvta_generic_to_shared(sg);

    const int tid  = threadIdx.x;
    const int lane = tid & 31;
    const int warp = tid >> 5;
    const int g = lane >> 2;
    const int q = lane & 3;
    const int wm = warp >> 2;       // 0..1 -> rows wm*64
    const int wn = warp & 3;        // 0..3 -> cols wn*32
    const int n0 = blockIdx.x * GBN;
    const int m0 = blockIdx.y * GBM;

    auto cpBlk = [&](int kb, int buf) {
        const float* src = (kb < DD) ? g_xtf : g_ctx;
        const int koff = kb & (DD - 1);
        const int bx = buf ? GX1 : GX0;
        const int bw = buf ? GW1 : GW0;
        #pragma unroll
        for (int t = 0; t < 4; t++) {
            int idx = tid + t * GT;             // 0..1023
            int r = idx >> 3, c4 = idx & 7;     // row 0..127, float4 col 0..7
            unsigned sa = sbase + (unsigned)(bx + r * GLDS + c4 * 4) * 4u;
            cp16(sa, src + (size_t)(m0 + r) * DD + koff + c4 * 4);
            unsigned sw = sbase + (unsigned)(bw + r * GLDS + c4 * 4) * 4u;
            cp16(sw, g_wtf + (size_t)(n0 + r) * (2 * DD) + kb + c4 * 4);
        }
        asm volatile("cp.async.commit_group;\n" ::: "memory");
    };
    cpBlk(0, 0);

    float acc[4][4][4] = {};
    int buf = 0;

    for (int kb = 0; kb < 2 * DD; kb += GBK) {
        asm volatile("cp.async.wait_group 0;\n" ::: "memory");
        __syncthreads();
        if (kb + GBK < 2 * DD) cpBlk(kb + GBK, buf ^ 1);

        const float* sX = sg + (buf ? GX1 : GX0);
        const float* sW = sg + (buf ? GW1 : GW0);

        #pragma unroll
        for (int kk = 0; kk < GBK; kk += 8) {
            unsigned a[4][4], bb[4][2];
            #pragma unroll
            for (int mi = 0; mi < 4; mi++) {
                const float* xp = sX + kk + q;
                int r0 = wm * 64 + mi * 16;
                a[mi][0] = __float_as_uint(xp[(r0 + g) * GLDS]);
                a[mi][1] = __float_as_uint(xp[(r0 + g + 8) * GLDS]);
                a[mi][2] = __float_as_uint(xp[(r0 + g) * GLDS + 4]);
                a[mi][3] = __float_as_uint(xp[(r0 + g + 8) * GLDS + 4]);
            }
            #pragma unroll
            for (int ni = 0; ni < 4; ni++) {
                int nw = wn * 32 + ni * 8;
                bb[ni][0] = __float_as_uint(sW[(nw + g) * GLDS + kk + q]);
                bb[ni][1] = __float_as_uint(sW[(nw + g) * GLDS + kk + q + 4]);
            }
            #pragma unroll
            for (int mi = 0; mi < 4; mi++)
                #pragma unroll
                for (int ni = 0; ni < 4; ni++)
                    mma_tf32(acc[mi][ni], a[mi], bb[ni]);
        }
        buf ^= 1;
    }

    // ---- epilogue: bias + sigmoid*tanh, direct to global ----
    #pragma unroll
    for (int ni = 0; ni < 4; ni++) {
        int col = n0 + wn * 32 + ni * 8 + 2 * q;
        float b0 = bc[col], b1 = bc[col + 1];
        #pragma unroll
        for (int mi = 0; mi < 4; mi++) {
            int row = m0 + wm * 64 + mi * 16 + g;
            float2 v0, v1;
            v0.x = gated_act(acc[mi][ni][0] + b0);
            v0.y = gated_act(acc[mi][ni][1] + b1);
            v1.x = gated_act(acc[mi][ni][2] + b0);
            v1.y = gated_act(acc[mi][ni][3] + b1);
            *(float2*)&outp[(size_t)row * DD + col]       = v0;
            *(float2*)&outp[(size_t)(row + 8) * DD + col] = v1;
        }
    }
}

extern "C" void kernel_launch(void* const* d_in, const int* in_sizes, int n_in,
                              void* d_out, int out_size)
{
    const float* inp  = (const float*)d_in[0];   // [8,1024,1024]
    const float* mem  = (const float*)d_in[1];   // [8,1024,1024]
    const float* mask = (const float*)d_in[2];   // [8,1024]
    const float* Wc   = (const float*)d_in[3];   // [1024,2048]
    const float* bc   = (const float*)d_in[4];   // [1024]
    float* outp = (float*)d_out;                 // [8,1024,1024]

    const size_t att_smem = (size_t)ATT_SMEM_FLOATS * sizeof(float);
    cudaFuncSetAttribute(attn_kernel, cudaFuncAttributeMaxDynamicSharedMemorySize,
                         (int)att_smem);
    const size_t gemm_smem = (size_t)GEMM_SMEM_FLOATS * sizeof(float);
    cudaFuncSetAttribute(out_gemm_kernel, cudaFuncAttributeMaxDynamicSharedMemorySize,
                         (int)gemm_smem);

    // resolve device-scratch addresses (host side; legal under graph capture)
    float *xtf_p, *wtf_p;
    cudaGetSymbolAddress((void**)&xtf_p, g_xtf);
    cudaGetSymbolAddress((void**)&wtf_p, g_wtf);

    // prep: RN-round X and W once
    {
        int n4w = DD * 2 * DD / 4;       // 524288
        round_tf32_kernel<<<n4w / 256, 256>>>(Wc, wtf_p, n4w);
        int n4x = NB * SLD * DD / 4;     // 2097152
        round_tf32_kernel<<<n4x / 256, 256>>>(inp, xtf_p, n4x);
    }

    dim3 agrid(SLD / BQ, HH, NB);              // 16 x 16 x 8 = 2048 blocks
    attn_kernel<<<agrid, AT, att_smem>>>(inp, mem, mask);

    dim3 ggrid(DD / GBN, (NB * SLD) / GBM);    // 8 x 64 = 512 blocks
    out_gemm_kernel<<<ggrid, GT, gemm_smem>>>(bc, outp);
}

// round 7
// speedup vs baseline: 1.6179x; 1.0153x over previous
#include <cuda_runtime.h>
#include <cstdint>

#define NB  8
#define SLD 1024
#define SLM 1024
#define DD  1024
#define HH  16
#define HS  64

// Scratch: attention context (tf32-rounded), rounded X, rounded Wc, fp32 partial acc
__device__ float g_ctx[(size_t)NB * SLD * DD];        // 32 MB
__device__ float g_xtf[(size_t)NB * SLD * DD];        // 32 MB
__device__ float g_wtf[(size_t)DD * 2 * DD];          // 8 MB
__device__ float g_acc[(size_t)NB * SLD * DD];        // 32 MB

__device__ __forceinline__ void mma_tf32(float c[4], const unsigned a[4], const unsigned b[2]) {
    asm volatile(
        "mma.sync.aligned.m16n8k8.row.col.f32.tf32.tf32.f32 "
        "{%0,%1,%2,%3}, {%4,%5,%6,%7}, {%8,%9}, {%0,%1,%2,%3};\n"
        : "+f"(c[0]), "+f"(c[1]), "+f"(c[2]), "+f"(c[3])
        : "r"(a[0]), "r"(a[1]), "r"(a[2]), "r"(a[3]), "r"(b[0]), "r"(b[1]));
}

__device__ __forceinline__ void cp16(unsigned saddr, const float* gptr) {
    asm volatile("cp.async.cg.shared.global [%0], [%1], 16;\n" :: "r"(saddr), "l"(gptr));
}

__device__ __forceinline__ unsigned f2tf(float x) {
    unsigned u;
    asm("cvt.rna.tf32.f32 %0, %1;" : "=r"(u) : "f"(x));
    return u;
}

// ==================== prep: RN-round to tf32 in memory ====================
__global__ __launch_bounds__(256)
void round_tf32_kernel(const float* __restrict__ src, float* __restrict__ dst, int n4)
{
    int i = blockIdx.x * 256 + threadIdx.x;
    if (i < n4) {
        float4 v = ((const float4*)src)[i];
        v.x = __uint_as_float(f2tf(v.x));
        v.y = __uint_as_float(f2tf(v.y));
        v.z = __uint_as_float(f2tf(v.z));
        v.w = __uint_as_float(f2tf(v.w));
        ((float4*)dst)[i] = v;
    }
}

// ==================== fused flash-style attention (unchanged from R5) ====================
#define BQ 64
#define BK 64
#define AT 256
#define LDK 68

#define OFF_K0   0
#define OFF_K1   (64*LDK)
#define OFF_P    (2*64*LDK)
#define OFF_Q    (3*64*LDK)
#define OFF_M    (4*64*LDK)
#define OFF_RED  (OFF_M + 1024)
#define ATT_SMEM_FLOATS (OFF_RED + 64*4)   // 18688 floats = 74752 B

__global__ __launch_bounds__(AT, 3)
void attn_kernel(const float* __restrict__ inp,
                 const float* __restrict__ mem,
                 const float* __restrict__ maskp)
{
    extern __shared__ float sm[];
    const unsigned sbase = (unsigned)__cvta_generic_to_shared(sm);

    const int tid  = threadIdx.x;
    const int lane = tid & 31;
    const int warp = tid >> 5;
    const int g = lane >> 2;
    const int q = lane & 3;
    const int wm = warp >> 2;      // 0..1
    const int wn = warp & 3;       // 0..3
    const int qt = blockIdx.x, h = blockIdx.y, b = blockIdx.z;

    const float* kbase = mem + (size_t)b * SLM * DD + h * HS;

    auto cpK = [&](int kt, int buf) {
        const int base = buf ? OFF_K1 : OFF_K0;
        #pragma unroll
        for (int t = 0; t < 4; t++) {
            int idx = tid + t * AT;
            int r = idx >> 4, c4 = idx & 15;
            unsigned sa = sbase + (unsigned)(base + r * LDK + c4 * 4) * 4u;
            cp16(sa, kbase + (size_t)(kt * BK + r) * DD + c4 * 4);
        }
        asm volatile("cp.async.commit_group;\n" ::: "memory");
    };
    cpK(0, 0);

    const float* qbase = inp + ((size_t)(b * SLD + qt * BQ)) * DD + h * HS;
    #pragma unroll
    for (int t = 0; t < 4; t++) {
        int idx = tid + t * AT;
        int r = idx >> 4, c4 = idx & 15;
        float4 v = *(const float4*)(qbase + (size_t)r * DD + c4 * 4);
        v.x = __uint_as_float(f2tf(v.x)); v.y = __uint_as_float(f2tf(v.y));
        v.z = __uint_as_float(f2tf(v.z)); v.w = __uint_as_float(f2tf(v.w));
        *(float4*)&sm[OFF_Q + r * LDK + c4 * 4] = v;
    }
    for (int i = tid; i < SLM; i += AT)
        sm[OFF_M + i] = -1e30f * (1.0f - maskp[(size_t)b * SLM + i]);

    float oc[2][2][4] = {};
    float lpart[4] = {0.f, 0.f, 0.f, 0.f};
    int buf = 0;

    for (int kt = 0; kt < SLM / BK; kt++) {
        asm volatile("cp.async.wait_group 0;\n" ::: "memory");
        __syncthreads();
        if (kt + 1 < SLM / BK) cpK(kt + 1, buf ^ 1);

        const float* sK = sm + (buf ? OFF_K1 : OFF_K0);

        float sc[2][2][4] = {};
        #pragma unroll
        for (int kk = 0; kk < 8; kk++) {
            unsigned a[2][4], bb[2][2];
            #pragma unroll
            for (int mf = 0; mf < 2; mf++) {
                const float* qp = sm + OFF_Q + kk * 8 + q;
                int r0 = wm * 32 + mf * 16;
                a[mf][0] = __float_as_uint(qp[(r0 + g) * LDK]);
                a[mf][1] = __float_as_uint(qp[(r0 + g + 8) * LDK]);
                a[mf][2] = __float_as_uint(qp[(r0 + g) * LDK + 4]);
                a[mf][3] = __float_as_uint(qp[(r0 + g + 8) * LDK + 4]);
            }
            #pragma unroll
            for (int nf = 0; nf < 2; nf++) {
                int n0 = wn * 16 + nf * 8;
                bb[nf][0] = __float_as_uint(sK[(n0 + g) * LDK + kk * 8 + q]);
                bb[nf][1] = __float_as_uint(sK[(n0 + g) * LDK + kk * 8 + q + 4]);
            }
            #pragma unroll
            for (int mf = 0; mf < 2; mf++)
                #pragma unroll
                for (int nf = 0; nf < 2; nf++)
                    mma_tf32(sc[mf][nf], a[mf], bb[nf]);
        }

        #pragma unroll
        for (int mf = 0; mf < 2; mf++) {
            int row = wm * 32 + mf * 16;
            #pragma unroll
            for (int nf = 0; nf < 2; nf++) {
                int col = wn * 16 + nf * 8 + 2 * q;
                float m0v = sm[OFF_M + kt * 64 + col];
                float m1v = sm[OFF_M + kt * 64 + col + 1];
                float p0 = __expf(sc[mf][nf][0] * 0.125f + m0v);
                float p1 = __expf(sc[mf][nf][1] * 0.125f + m1v);
                float p2 = __expf(sc[mf][nf][2] * 0.125f + m0v);
                float p3 = __expf(sc[mf][nf][3] * 0.125f + m1v);
                lpart[mf * 2 + 0] += p0 + p1;
                lpart[mf * 2 + 1] += p2 + p3;
                *(float2*)&sm[OFF_P + (row + g) * LDK + col]     = make_float2(p0, p1);
                *(float2*)&sm[OFF_P + (row + g + 8) * LDK + col] = make_float2(p2, p3);
            }
        }
        __syncthreads();

        #pragma unroll
        for (int kk = 0; kk < 8; kk++) {
            unsigned a[2][4], bb[2][2];
            #pragma unroll
            for (int mf = 0; mf < 2; mf++) {
                const float* pp = sm + OFF_P + kk * 8 + q;
                int r0 = wm * 32 + mf * 16;
                a[mf][0] = __float_as_uint(pp[(r0 + g) * LDK]);
                a[mf][1] = __float_as_uint(pp[(r0 + g + 8) * LDK]);
                a[mf][2] = __float_as_uint(pp[(r0 + g) * LDK + 4]);
                a[mf][3] = __float_as_uint(pp[(r0 + g + 8) * LDK + 4]);
            }
            #pragma unroll
            for (int nf = 0; nf < 2; nf++) {
                int n0 = wn * 16 + nf * 8;
                bb[nf][0] = __float_as_uint(sK[(kk * 8 + q) * LDK + n0 + g]);
                bb[nf][1] = __float_as_uint(sK[(kk * 8 + q + 4) * LDK + n0 + g]);
            }
            #pragma unroll
            for (int mf = 0; mf < 2; mf++)
                #pragma unroll
                for (int nf = 0; nf < 2; nf++)
                    mma_tf32(oc[mf][nf], a[mf], bb[nf]);
        }
        buf ^= 1;
    }

    #pragma unroll
    for (int i = 0; i < 4; i++) {
        lpart[i] += __shfl_xor_sync(0xffffffffu, lpart[i], 1);
        lpart[i] += __shfl_xor_sync(0xffffffffu, lpart[i], 2);
    }
    if (q == 0) {
        #pragma unroll
        for (int mf = 0; mf < 2; mf++)
            #pragma unroll
            for (int rg = 0; rg < 2; rg++) {
                int row = wm * 32 + mf * 16 + g + rg * 8;
                sm[OFF_RED + row * 4 + wn] = lpart[mf * 2 + rg];
            }
    }
    __syncthreads();

    float* obase = g_ctx + ((size_t)(b * SLD + qt * BQ)) * DD + h * HS;
    #pragma unroll
    for (int mf = 0; mf < 2; mf++) {
        #pragma unroll
        for (int rg = 0; rg < 2; rg++) {
            int row = wm * 32 + mf * 16 + g + rg * 8;
            float L = sm[OFF_RED + row * 4 + 0] + sm[OFF_RED + row * 4 + 1]
                    + sm[OFF_RED + row * 4 + 2] + sm[OFF_RED + row * 4 + 3];
            float inv = 1.0f / L;
            #pragma unroll
            for (int nf = 0; nf < 2; nf++) {
                float2 v;
                v.x = __uint_as_float(f2tf(oc[mf][nf][rg * 2 + 0] * inv));
                v.y = __uint_as_float(f2tf(oc[mf][nf][rg * 2 + 1] * inv));
                *(float2*)&obase[(size_t)row * DD + wn * 16 + nf * 8 + 2 * q] = v;
            }
        }
    }
}

// ==================== half GEMM (K=1024) + optional epilogue ====================
// acc_out[m][n] (+)= sum_k src[m][k] * wbase[n*2048 + k],  k in [0,1024)
// final_pass=0: store raw fp32 partials to accp.
// final_pass=1: out = act(acc + accp + bc), act(o)=sigmoid(o)*tanh(o).
// CTA tile 128x128x32, 256 threads, warp grid 2x4 (warp tile 64x32), 3-stage cp.async ring.
#define TM2 128
#define TN2 128
#define GBK 32
#define GLDS 36
#define GT2 256
#define STG_FLOATS ((TM2 + TN2) * GLDS)          // 9216 floats per stage
#define GEMM_SMEM_BYTES (3 * STG_FLOATS * 4)     // 110592 B

__device__ __forceinline__ float gated_act(float o) {
    o = fminf(fmaxf(o, -30.0f), 30.0f);
    float e = __expf(-o);
    return (1.0f - e) / (1.0f + e * e);   // == sigmoid(o)*tanh(o)
}

__global__ __launch_bounds__(GT2, 2)
void half_gemm_kernel(const float* __restrict__ src,
                      const float* __restrict__ wbase,
                      const float* __restrict__ bc,
                      float* __restrict__ accp,
                      float* __restrict__ outp,
                      int final_pass)
{
    extern __shared__ float sg[];
    const unsigned sbase = (unsigned)__cvta_generic_to_shared(sg);

    const int tid  = threadIdx.x;
    const int lane = tid & 31;
    const int warp = tid >> 5;
    const int g = lane >> 2;
    const int q = lane & 3;
    const int wm = warp >> 2;       // 0..1 -> rows wm*64
    const int wn = warp & 3;        // 0..3 -> cols wn*32
    const int n0 = blockIdx.x * TN2;
    const int m0 = blockIdx.y * TM2;

    auto stage = [&](int kb, int s) {
        const unsigned bx = sbase + (unsigned)(s * STG_FLOATS) * 4u;
        const unsigned bw = bx + (unsigned)(TM2 * GLDS) * 4u;
        #pragma unroll
        for (int t = 0; t < 4; t++) {
            int idx = tid + t * GT2;            // 0..1023
            int r = idx >> 3, c4 = idx & 7;     // row 0..127, float4 col 0..7
            cp16(bx + (unsigned)(r * GLDS + c4 * 4) * 4u,
                 src + (size_t)(m0 + r) * DD + kb + c4 * 4);
            cp16(bw + (unsigned)(r * GLDS + c4 * 4) * 4u,
                 wbase + (size_t)(n0 + r) * (2 * DD) + kb + c4 * 4);
        }
        asm volatile("cp.async.commit_group;" ::: "memory");
    };

    stage(0, 0);
    stage(GBK, 1);

    float acc[4][4][4] = {};

    for (int i = 0; i < DD / GBK; i++) {        // 32 iterations
        if (i + 1 < DD / GBK)
            asm volatile("cp.async.wait_group 1;" ::: "memory");
        else
            asm volatile("cp.async.wait_group 0;" ::: "memory");
        __syncthreads();
        if (i + 2 < DD / GBK) stage((i + 2) * GBK, (i + 2) % 3);

        const float* sX = sg + (i % 3) * STG_FLOATS;
        const float* sW = sX + TM2 * GLDS;

        #pragma unroll
        for (int kk = 0; kk < GBK; kk += 8) {
            unsigned a[4][4], bb[4][2];
            #pragma unroll
            for (int mi = 0; mi < 4; mi++) {
                const float* xp = sX + kk + q;
                int r0 = wm * 64 + mi * 16;
                a[mi][0] = __float_as_uint(xp[(r0 + g) * GLDS]);
                a[mi][1] = __float_as_uint(xp[(r0 + g + 8) * GLDS]);
                a[mi][2] = __float_as_uint(xp[(r0 + g) * GLDS + 4]);
                a[mi][3] = __float_as_uint(xp[(r0 + g + 8) * GLDS + 4]);
            }
            #pragma unroll
            for (int ni = 0; ni < 4; ni++) {
                int nw = wn * 32 + ni * 8;
                bb[ni][0] = __float_as_uint(sW[(nw + g) * GLDS + kk + q]);
                bb[ni][1] = __float_as_uint(sW[(nw + g) * GLDS + kk + q + 4]);
            }
            #pragma unroll
            for (int mi = 0; mi < 4; mi++)
                #pragma unroll
                for (int ni = 0; ni < 4; ni++)
                    mma_tf32(acc[mi][ni], a[mi], bb[ni]);
        }
    }

    if (final_pass) {
        #pragma unroll
        for (int ni = 0; ni < 4; ni++) {
            int col = n0 + wn * 32 + ni * 8 + 2 * q;
            float b0 = bc[col], b1 = bc[col + 1];
            #pragma unroll
            for (int mi = 0; mi < 4; mi++) {
                int row = m0 + wm * 64 + mi * 16 + g;
                float2 p0 = *(const float2*)&accp[(size_t)row * DD + col];
                float2 p1 = *(const float2*)&accp[(size_t)(row + 8) * DD + col];
                float2 v0, v1;
                v0.x = gated_act(acc[mi][ni][0] + p0.x + b0);
                v0.y = gated_act(acc[mi][ni][1] + p0.y + b1);
                v1.x = gated_act(acc[mi][ni][2] + p1.x + b0);
                v1.y = gated_act(acc[mi][ni][3] + p1.y + b1);
                *(float2*)&outp[(size_t)row * DD + col]       = v0;
                *(float2*)&outp[(size_t)(row + 8) * DD + col] = v1;
            }
        }
    } else {
        #pragma unroll
        for (int ni = 0; ni < 4; ni++) {
            int col = n0 + wn * 32 + ni * 8 + 2 * q;
            #pragma unroll
            for (int mi = 0; mi < 4; mi++) {
                int row = m0 + wm * 64 + mi * 16 + g;
                *(float2*)&accp[(size_t)row * DD + col] =
                    make_float2(acc[mi][ni][0], acc[mi][ni][1]);
                *(float2*)&accp[(size_t)(row + 8) * DD + col] =
                    make_float2(acc[mi][ni][2], acc[mi][ni][3]);
            }
        }
    }
}

extern "C" void kernel_launch(void* const* d_in, const int* in_sizes, int n_in,
                              void* d_out, int out_size)
{
    const float* inp  = (const float*)d_in[0];   // [8,1024,1024]
    const float* mem  = (const float*)d_in[1];   // [8,1024,1024]
    const float* mask = (const float*)d_in[2];   // [8,1024]
    const float* Wc   = (const float*)d_in[3];   // [1024,2048]
    const float* bc   = (const float*)d_in[4];   // [1024]
    float* outp = (float*)d_out;                 // [8,1024,1024]

    // one-time setup (first call = correctness run, NOT under graph capture)
    static cudaStream_t s2 = nullptr;
    static cudaEvent_t evFork = nullptr, evJoin = nullptr;
    if (!s2) {
        cudaStreamCreate(&s2);
        cudaEventCreateWithFlags(&evFork, cudaEventDisableTiming);
        cudaEventCreateWithFlags(&evJoin, cudaEventDisableTiming);
        cudaFuncSetAttribute(attn_kernel, cudaFuncAttributeMaxDynamicSharedMemorySize,
                             (int)(ATT_SMEM_FLOATS * sizeof(float)));
        cudaFuncSetAttribute(half_gemm_kernel, cudaFuncAttributeMaxDynamicSharedMemorySize,
                             GEMM_SMEM_BYTES);
    }

    float *xtf_p, *wtf_p, *ctx_p, *acc_p;
    cudaGetSymbolAddress((void**)&xtf_p, g_xtf);
    cudaGetSymbolAddress((void**)&wtf_p, g_wtf);
    cudaGetSymbolAddress((void**)&ctx_p, g_ctx);
    cudaGetSymbolAddress((void**)&acc_p, g_acc);

    // fork side stream from stream 0
    cudaEventRecord(evFork, 0);
    cudaStreamWaitEvent(s2, evFork, 0);

    // s2: round W and X, then X-half GEMM into g_acc (independent of attention)
    {
        int n4w = DD * 2 * DD / 4;       // 524288
        round_tf32_kernel<<<n4w / 256, 256, 0, s2>>>(Wc, wtf_p, n4w);
        int n4x = NB * SLD * DD / 4;     // 2097152
        round_tf32_kernel<<<n4x / 256, 256, 0, s2>>>(inp, xtf_p, n4x);
        dim3 ggrid(DD / TN2, (NB * SLD) / TM2);    // 8 x 64 = 512 blocks
        half_gemm_kernel<<<ggrid, GT2, GEMM_SMEM_BYTES, s2>>>(
            xtf_p, wtf_p, bc, acc_p, outp, 0);
    }
    cudaEventRecord(evJoin, s2);

    // stream 0: attention (concurrent with s2)
    dim3 agrid(SLD / BQ, HH, NB);              // 16 x 16 x 8 = 2048 blocks
    attn_kernel<<<agrid, AT, ATT_SMEM_FLOATS * sizeof(float)>>>(inp, mem, mask);

    // join, then C-half GEMM + epilogue
    cudaStreamWaitEvent(0, evJoin, 0);
    dim3 ggrid(DD / TN2, (NB * SLD) / TM2);
    half_gemm_kernel<<<ggrid, GT2, GEMM_SMEM_BYTES>>>(
        ctx_p, wtf_p + DD, bc, acc_p, outp, 1);
}

// round 8
// speedup vs baseline: 1.6443x; 1.0163x over previous
#include <cuda_runtime.h>
#include <cstdint>

#define NB  8
#define SLD 1024
#define SLM 1024
#define DD  1024
#define HH  16
#define HS  64

// Scratch: attention context (tf32-rounded), rounded X, rounded Wc, fp32 partial acc
__device__ float g_ctx[(size_t)NB * SLD * DD];        // 32 MB
__device__ float g_xtf[(size_t)NB * SLD * DD];        // 32 MB
__device__ float g_wtf[(size_t)DD * 2 * DD];          // 8 MB
__device__ float g_acc[(size_t)NB * SLD * DD];        // 32 MB

__device__ __forceinline__ void mma_tf32(float c[4], const unsigned a[4], const unsigned b[2]) {
    asm volatile(
        "mma.sync.aligned.m16n8k8.row.col.f32.tf32.tf32.f32 "
        "{%0,%1,%2,%3}, {%4,%5,%6,%7}, {%8,%9}, {%0,%1,%2,%3};\n"
        : "+f"(c[0]), "+f"(c[1]), "+f"(c[2]), "+f"(c[3])
        : "r"(a[0]), "r"(a[1]), "r"(a[2]), "r"(a[3]), "r"(b[0]), "r"(b[1]));
}

__device__ __forceinline__ void cp16(unsigned saddr, const float* gptr) {
    asm volatile("cp.async.cg.shared.global [%0], [%1], 16;\n" :: "r"(saddr), "l"(gptr));
}

__device__ __forceinline__ unsigned f2tf(float x) {
    unsigned u;
    asm("cvt.rna.tf32.f32 %0, %1;" : "=r"(u) : "f"(x));
    return u;
}

// ==================== prep: RN-round to tf32 in memory ====================
__global__ __launch_bounds__(256)
void round_tf32_kernel(const float* __restrict__ src, float* __restrict__ dst, int n4)
{
    int i = blockIdx.x * 256 + threadIdx.x;
    if (i < n4) {
        float4 v = ((const float4*)src)[i];
        v.x = __uint_as_float(f2tf(v.x));
        v.y = __uint_as_float(f2tf(v.y));
        v.z = __uint_as_float(f2tf(v.z));
        v.w = __uint_as_float(f2tf(v.w));
        ((float4*)dst)[i] = v;
    }
}

// ==================== flash attention, register-resident P ====================
// BQ=128, 8 warps; each warp: 16 query rows x all 64 keys of the tile.
// S and O accumulators + P conversion all in registers (shfl-based layout fix).
#define BQ 128
#define BK 64
#define AT 256
#define LDK 68

#define OFF_K0   0
#define OFF_K1   (64*LDK)            // 4352
#define OFF_Q    (2*64*LDK)          // 8704, Q tile 128*68
#define OFF_M    (OFF_Q + BQ*LDK)    // 17408
#define ATT_SMEM_FLOATS (OFF_M + 1024)   // 18432 floats = 73728 B

__global__ __launch_bounds__(AT, 2)
void attn_kernel(const float* __restrict__ inp,
                 const float* __restrict__ mem,
                 const float* __restrict__ maskp)
{
    extern __shared__ float sm[];
    const unsigned sbase = (unsigned)__cvta_generic_to_shared(sm);

    const int tid  = threadIdx.x;
    const int lane = tid & 31;
    const int warp = tid >> 5;
    const int g = lane >> 2;       // 0..7
    const int q = lane & 3;        // 0..3
    const int qt = blockIdx.x, h = blockIdx.y, b = blockIdx.z;
    const int qrow = warp * 16;    // warp's first query row in tile

    const float* kbase = mem + (size_t)b * SLM * DD + h * HS;

    auto cpK = [&](int kt, int buf) {
        const int base = buf ? OFF_K1 : OFF_K0;
        #pragma unroll
        for (int t = 0; t < 4; t++) {
            int idx = tid + t * AT;            // 0..1023
            int r = idx >> 4, c4 = idx & 15;   // key row 0..63, float4 col
            unsigned sa = sbase + (unsigned)(base + r * LDK + c4 * 4) * 4u;
            cp16(sa, kbase + (size_t)(kt * BK + r) * DD + c4 * 4);
        }
        asm volatile("cp.async.commit_group;\n" ::: "memory");
    };
    cpK(0, 0);

    // stage Q tile [128][64] (RN-rounded) and additive mask row
    const float* qbase = inp + ((size_t)(b * SLD + qt * BQ)) * DD + h * HS;
    #pragma unroll
    for (int t = 0; t < 8; t++) {
        int idx = tid + t * AT;                // 0..2047 float4s
        int r = idx >> 4, c4 = idx & 15;
        float4 v = *(const float4*)(qbase + (size_t)r * DD + c4 * 4);
        v.x = __uint_as_float(f2tf(v.x)); v.y = __uint_as_float(f2tf(v.y));
        v.z = __uint_as_float(f2tf(v.z)); v.w = __uint_as_float(f2tf(v.w));
        *(float4*)&sm[OFF_Q + r * LDK + c4 * 4] = v;
    }
    for (int i = tid; i < SLM; i += AT)
        sm[OFF_M + i] = -1e30f * (1.0f - maskp[(size_t)b * SLM + i]);

    float oc[8][4] = {};
    float l0 = 0.f, l1 = 0.f;
    int buf = 0;
    const int srcA = (lane & ~3) | (q >> 1);
    const int srcB = srcA + 2;
    const bool sel = (q & 1);

    for (int kt = 0; kt < SLM / BK; kt++) {
        asm volatile("cp.async.wait_group 0;\n" ::: "memory");
        __syncthreads();
        if (kt + 1 < SLM / BK) cpK(kt + 1, buf ^ 1);

        const float* sK = sm + (buf ? OFF_K1 : OFF_K0);

        // ---- S = Q K^T : 16 rows x 64 keys per warp ----
        float sc[8][4] = {};
        #pragma unroll
        for (int kk = 0; kk < 8; kk++) {
            unsigned a[4];
            const float* qp = sm + OFF_Q + kk * 8 + q;
            a[0] = __float_as_uint(qp[(qrow + g) * LDK]);
            a[1] = __float_as_uint(qp[(qrow + g + 8) * LDK]);
            a[2] = __float_as_uint(qp[(qrow + g) * LDK + 4]);
            a[3] = __float_as_uint(qp[(qrow + g + 8) * LDK + 4]);
            #pragma unroll
            for (int j = 0; j < 8; j++) {
                unsigned bb[2];
                bb[0] = __float_as_uint(sK[(j * 8 + g) * LDK + kk * 8 + q]);
                bb[1] = __float_as_uint(sK[(j * 8 + g) * LDK + kk * 8 + q + 4]);
                mma_tf32(sc[j], a, bb);
            }
        }

        // ---- p = exp(s/8 + maskadd); row-sum partials (regs only) ----
        #pragma unroll
        for (int j = 0; j < 8; j++) {
            float2 mv = *(const float2*)&sm[OFF_M + kt * 64 + j * 8 + 2 * q];
            float p0 = __expf(sc[j][0] * 0.125f + mv.x);
            float p1 = __expf(sc[j][1] * 0.125f + mv.y);
            float p2 = __expf(sc[j][2] * 0.125f + mv.x);
            float p3 = __expf(sc[j][3] * 0.125f + mv.y);
            l0 += p0 + p1;
            l1 += p2 + p3;
            sc[j][0] = p0; sc[j][1] = p1; sc[j][2] = p2; sc[j][3] = p3;
        }

        // ---- O += P V : convert acc->A-frag via shfl, then mma over hs ----
        #pragma unroll
        for (int j = 0; j < 8; j++) {
            float t0 = __shfl_sync(0xffffffffu, sc[j][0], srcA);
            float t1 = __shfl_sync(0xffffffffu, sc[j][1], srcA);
            float t2 = __shfl_sync(0xffffffffu, sc[j][2], srcA);
            float t3 = __shfl_sync(0xffffffffu, sc[j][3], srcA);
            float u0 = __shfl_sync(0xffffffffu, sc[j][0], srcB);
            float u1 = __shfl_sync(0xffffffffu, sc[j][1], srcB);
            float u2 = __shfl_sync(0xffffffffu, sc[j][2], srcB);
            float u3 = __shfl_sync(0xffffffffu, sc[j][3], srcB);
            unsigned a[4];
            a[0] = __float_as_uint(sel ? t1 : t0);   // P(g,     8j+q)
            a[1] = __float_as_uint(sel ? t3 : t2);   // P(g+8,   8j+q)
            a[2] = __float_as_uint(sel ? u1 : u0);   // P(g,   8j+q+4)
            a[3] = __float_as_uint(sel ? u3 : u2);   // P(g+8, 8j+q+4)
            #pragma unroll
            for (int nf = 0; nf < 8; nf++) {
                unsigned bb[2];
                bb[0] = __float_as_uint(sK[(j * 8 + q) * LDK + nf * 8 + g]);
                bb[1] = __float_as_uint(sK[(j * 8 + q + 4) * LDK + nf * 8 + g]);
                mma_tf32(oc[nf], a, bb);
            }
        }
        buf ^= 1;
    }

    // ---- complete row sums within the warp (cols live across q-lanes) ----
    l0 += __shfl_xor_sync(0xffffffffu, l0, 1);
    l0 += __shfl_xor_sync(0xffffffffu, l0, 2);
    l1 += __shfl_xor_sync(0xffffffffu, l1, 1);
    l1 += __shfl_xor_sync(0xffffffffu, l1, 2);
    const float inv0 = 1.0f / l0;   // row qrow+g
    const float inv1 = 1.0f / l1;   // row qrow+g+8

    // ---- normalize, RN-round to tf32, write context ----
    float* obase = g_ctx + ((size_t)(b * SLD + qt * BQ + qrow)) * DD + h * HS;
    #pragma unroll
    for (int nf = 0; nf < 8; nf++) {
        float2 v;
        v.x = __uint_as_float(f2tf(oc[nf][0] * inv0));
        v.y = __uint_as_float(f2tf(oc[nf][1] * inv0));
        *(float2*)&obase[(size_t)g * DD + nf * 8 + 2 * q] = v;
        v.x = __uint_as_float(f2tf(oc[nf][2] * inv1));
        v.y = __uint_as_float(f2tf(oc[nf][3] * inv1));
        *(float2*)&obase[(size_t)(g + 8) * DD + nf * 8 + 2 * q] = v;
    }
}

// ==================== half GEMM (K=1024) + optional epilogue ====================
#define TM2 128
#define TN2 128
#define GBK 32
#define GLDS 36
#define GT2 256
#define STG_FLOATS ((TM2 + TN2) * GLDS)          // 9216 floats per stage
#define GEMM_SMEM_BYTES (3 * STG_FLOATS * 4)     // 110592 B

__device__ __forceinline__ float gated_act(float o) {
    o = fminf(fmaxf(o, -30.0f), 30.0f);
    float e = __expf(-o);
    return (1.0f - e) / (1.0f + e * e);   // == sigmoid(o)*tanh(o)
}

__global__ __launch_bounds__(GT2, 2)
void half_gemm_kernel(const float* __restrict__ src,
                      const float* __restrict__ wbase,
                      const float* __restrict__ bc,
                      float* __restrict__ accp,
                      float* __restrict__ outp,
                      int final_pass)
{
    extern __shared__ float sg[];
    const unsigned sbase = (unsigned)__cvta_generic_to_shared(sg);

    const int tid  = threadIdx.x;
    const int lane = tid & 31;
    const int warp = tid >> 5;
    const int g = lane >> 2;
    const int q = lane & 3;
    const int wm = warp >> 2;       // 0..1 -> rows wm*64
    const int wn = warp & 3;        // 0..3 -> cols wn*32
    const int n0 = blockIdx.x * TN2;
    const int m0 = blockIdx.y * TM2;

    auto stage = [&](int kb, int s) {
        const unsigned bx = sbase + (unsigned)(s * STG_FLOATS) * 4u;
        const unsigned bw = bx + (unsigned)(TM2 * GLDS) * 4u;
        #pragma unroll
        for (int t = 0; t < 4; t++) {
            int idx = tid + t * GT2;            // 0..1023
            int r = idx >> 3, c4 = idx & 7;     // row 0..127, float4 col 0..7
            cp16(bx + (unsigned)(r * GLDS + c4 * 4) * 4u,
                 src + (size_t)(m0 + r) * DD + kb + c4 * 4);
            cp16(bw + (unsigned)(r * GLDS + c4 * 4) * 4u,
                 wbase + (size_t)(n0 + r) * (2 * DD) + kb + c4 * 4);
        }
        asm volatile("cp.async.commit_group;" ::: "memory");
    };

    stage(0, 0);
    stage(GBK, 1);

    float acc[4][4][4] = {};

    for (int i = 0; i < DD / GBK; i++) {        // 32 iterations
        if (i + 1 < DD / GBK)
            asm volatile("cp.async.wait_group 1;" ::: "memory");
        else
            asm volatile("cp.async.wait_group 0;" ::: "memory");
        __syncthreads();
        if (i + 2 < DD / GBK) stage((i + 2) * GBK, (i + 2) % 3);

        const float* sX = sg + (i % 3) * STG_FLOATS;
        const float* sW = sX + TM2 * GLDS;

        #pragma unroll
        for (int kk = 0; kk < GBK; kk += 8) {
            unsigned a[4][4], bb[4][2];
            #pragma unroll
            for (int mi = 0; mi < 4; mi++) {
                const float* xp = sX + kk + q;
                int r0 = wm * 64 + mi * 16;
                a[mi][0] = __float_as_uint(xp[(r0 + g) * GLDS]);
                a[mi][1] = __float_as_uint(xp[(r0 + g + 8) * GLDS]);
                a[mi][2] = __float_as_uint(xp[(r0 + g) * GLDS + 4]);
                a[mi][3] = __float_as_uint(xp[(r0 + g + 8) * GLDS + 4]);
            }
            #pragma unroll
            for (int ni = 0; ni < 4; ni++) {
                int nw = wn * 32 + ni * 8;
                bb[ni][0] = __float_as_uint(sW[(nw + g) * GLDS + kk + q]);
                bb[ni][1] = __float_as_uint(sW[(nw + g) * GLDS + kk + q + 4]);
            }
            #pragma unroll
            for (int mi = 0; mi < 4; mi++)
                #pragma unroll
                for (int ni = 0; ni < 4; ni++)
                    mma_tf32(acc[mi][ni], a[mi], bb[ni]);
        }
    }

    if (final_pass) {
        #pragma unroll
        for (int ni = 0; ni < 4; ni++) {
            int col = n0 + wn * 32 + ni * 8 + 2 * q;
            float b0 = bc[col], b1 = bc[col + 1];
            #pragma unroll
            for (int mi = 0; mi < 4; mi++) {
                int row = m0 + wm * 64 + mi * 16 + g;
                float2 p0 = *(const float2*)&accp[(size_t)row * DD + col];
                float2 p1 = *(const float2*)&accp[(size_t)(row + 8) * DD + col];
                float2 v0, v1;
                v0.x = gated_act(acc[mi][ni][0] + p0.x + b0);
                v0.y = gated_act(acc[mi][ni][1] + p0.y + b1);
                v1.x = gated_act(acc[mi][ni][2] + p1.x + b0);
                v1.y = gated_act(acc[mi][ni][3] + p1.y + b1);
                *(float2*)&outp[(size_t)row * DD + col]       = v0;
                *(float2*)&outp[(size_t)(row + 8) * DD + col] = v1;
            }
        }
    } else {
        #pragma unroll
        for (int ni = 0; ni < 4; ni++) {
            int col = n0 + wn * 32 + ni * 8 + 2 * q;
            #pragma unroll
            for (int mi = 0; mi < 4; mi++) {
                int row = m0 + wm * 64 + mi * 16 + g;
                *(float2*)&accp[(size_t)row * DD + col] =
                    make_float2(acc[mi][ni][0], acc[mi][ni][1]);
                *(float2*)&accp[(size_t)(row + 8) * DD + col] =
                    make_float2(acc[mi][ni][2], acc[mi][ni][3]);
            }
        }
    }
}

extern "C" void kernel_launch(void* const* d_in, const int* in_sizes, int n_in,
                              void* d_out, int out_size)
{
    const float* inp  = (const float*)d_in[0];   // [8,1024,1024]
    const float* mem  = (const float*)d_in[1];   // [8,1024,1024]
    const float* mask = (const float*)d_in[2];   // [8,1024]
    const float* Wc   = (const float*)d_in[3];   // [1024,2048]
    const float* bc   = (const float*)d_in[4];   // [1024]
    float* outp = (float*)d_out;                 // [8,1024,1024]

    // one-time setup (first call = correctness run, NOT under graph capture)
    static cudaStream_t s2 = nullptr;
    static cudaEvent_t evFork = nullptr, evJoin = nullptr;
    if (!s2) {
        cudaStreamCreate(&s2);
        cudaEventCreateWithFlags(&evFork, cudaEventDisableTiming);
        cudaEventCreateWithFlags(&evJoin, cudaEventDisableTiming);
        cudaFuncSetAttribute(attn_kernel, cudaFuncAttributeMaxDynamicSharedMemorySize,
                             (int)(ATT_SMEM_FLOATS * sizeof(float)));
        cudaFuncSetAttribute(half_gemm_kernel, cudaFuncAttributeMaxDynamicSharedMemorySize,
                             GEMM_SMEM_BYTES);
    }

    float *xtf_p, *wtf_p, *ctx_p, *acc_p;
    cudaGetSymbolAddress((void**)&xtf_p, g_xtf);
    cudaGetSymbolAddress((void**)&wtf_p, g_wtf);
    cudaGetSymbolAddress((void**)&ctx_p, g_ctx);
    cudaGetSymbolAddress((void**)&acc_p, g_acc);

    // fork side stream from stream 0
    cudaEventRecord(evFork, 0);
    cudaStreamWaitEvent(s2, evFork, 0);

    // s2: round W and X, then X-half GEMM into g_acc (independent of attention)
    {
        int n4w = DD * 2 * DD / 4;       // 524288
        round_tf32_kernel<<<n4w / 256, 256, 0, s2>>>(Wc, wtf_p, n4w);
        int n4x = NB * SLD * DD / 4;     // 2097152
        round_tf32_kernel<<<n4x / 256, 256, 0, s2>>>(inp, xtf_p, n4x);
        dim3 ggrid(DD / TN2, (NB * SLD) / TM2);    // 8 x 64 = 512 blocks
        half_gemm_kernel<<<ggrid, GT2, GEMM_SMEM_BYTES, s2>>>(
            xtf_p, wtf_p, bc, acc_p, outp, 0);
    }
    cudaEventRecord(evJoin, s2);

    // stream 0: attention (concurrent with s2)
    dim3 agrid(SLD / BQ, HH, NB);              // 8 x 16 x 8 = 1024 blocks
    attn_kernel<<<agrid, AT, ATT_SMEM_FLOATS * sizeof(float)>>>(inp, mem, mask);

    // join, then C-half GEMM + epilogue
    cudaStreamWaitEvent(0, evJoin, 0);
    dim3 ggrid(DD / TN2, (NB * SLD) / TM2);
    half_gemm_kernel<<<ggrid, GT2, GEMM_SMEM_BYTES>>>(
        ctx_p, wtf_p + DD, bc, acc_p, outp, 1);
}

// round 9
// speedup vs baseline: 1.9158x; 1.1651x over previous
#include <cuda_runtime.h>
#include <cstdint>

#define NB  8
#define SLD 1024
#define SLM 1024
#define DD  1024
#define HH  16
#define HS  64

// Scratch: attention context (tf32-rounded), rounded X, rounded Wc, fp32 partial acc
__device__ float g_ctx[(size_t)NB * SLD * DD];        // 32 MB
__device__ float g_xtf[(size_t)NB * SLD * DD];        // 32 MB
__device__ float g_wtf[(size_t)DD * 2 * DD];          // 8 MB
__device__ float g_acc[(size_t)NB * SLD * DD];        // 32 MB

__device__ __forceinline__ void mma_tf32(float c[4], const unsigned a[4], const unsigned b[2]) {
    asm volatile(
        "mma.sync.aligned.m16n8k8.row.col.f32.tf32.tf32.f32 "
        "{%0,%1,%2,%3}, {%4,%5,%6,%7}, {%8,%9}, {%0,%1,%2,%3};\n"
        : "+f"(c[0]), "+f"(c[1]), "+f"(c[2]), "+f"(c[3])
        : "r"(a[0]), "r"(a[1]), "r"(a[2]), "r"(a[3]), "r"(b[0]), "r"(b[1]));
}

__device__ __forceinline__ void cp16(unsigned saddr, const float* gptr) {
    asm volatile("cp.async.cg.shared.global [%0], [%1], 16;\n" :: "r"(saddr), "l"(gptr));
}

__device__ __forceinline__ unsigned f2tf(float x) {
    unsigned u;
    asm("cvt.rna.tf32.f32 %0, %1;" : "=r"(u) : "f"(x));
    return u;
}

// ==================== prep: RN-round to tf32 in memory ====================
__global__ __launch_bounds__(256)
void round_tf32_kernel(const float* __restrict__ src, float* __restrict__ dst, int n4)
{
    int i = blockIdx.x * 256 + threadIdx.x;
    if (i < n4) {
        float4 v = ((const float4*)src)[i];
        v.x = __uint_as_float(f2tf(v.x));
        v.y = __uint_as_float(f2tf(v.y));
        v.z = __uint_as_float(f2tf(v.z));
        v.w = __uint_as_float(f2tf(v.w));
        ((float4*)dst)[i] = v;
    }
}

// ==================== flash attention: 32 rows/warp, shared B-fragments ====================
// BQ=128, 4 warps; each warp: 32 query rows (2 m-frags) x all 64 keys.
// B-fragments (K tile) loaded once per (kk,j) and reused across both m-frags.
#define BQ 128
#define BK 64
#define AT 128
#define LDK 68

#define OFF_K0   0
#define OFF_K1   (64*LDK)            // 4352
#define OFF_Q    (2*64*LDK)          // 8704, Q tile 128*68
#define OFF_M    (OFF_Q + BQ*LDK)    // 17408
#define ATT_SMEM_FLOATS (OFF_M + 1024)   // 18432 floats = 73728 B

__global__ __launch_bounds__(AT, 2)
void attn_kernel(const float* __restrict__ inp,
                 const float* __restrict__ mem,
                 const float* __restrict__ maskp)
{
    extern __shared__ float sm[];
    const unsigned sbase = (unsigned)__cvta_generic_to_shared(sm);

    const int tid  = threadIdx.x;
    const int lane = tid & 31;
    const int warp = tid >> 5;     // 0..3
    const int g = lane >> 2;       // 0..7
    const int q = lane & 3;        // 0..3
    const int qt = blockIdx.x, h = blockIdx.y, b = blockIdx.z;
    const int qrow = warp * 32;    // warp's first query row in tile

    const float* kbase = mem + (size_t)b * SLM * DD + h * HS;

    auto cpK = [&](int kt, int buf) {
        const int base = buf ? OFF_K1 : OFF_K0;
        #pragma unroll
        for (int t = 0; t < 8; t++) {
            int idx = tid + t * AT;            // 0..1023
            int r = idx >> 4, c4 = idx & 15;   // key row 0..63, float4 col
            unsigned sa = sbase + (unsigned)(base + r * LDK + c4 * 4) * 4u;
            cp16(sa, kbase + (size_t)(kt * BK + r) * DD + c4 * 4);
        }
        asm volatile("cp.async.commit_group;\n" ::: "memory");
    };
    cpK(0, 0);

    // stage Q tile [128][64] (RN-rounded) and additive mask row
    const float* qbase = inp + ((size_t)(b * SLD + qt * BQ)) * DD + h * HS;
    #pragma unroll
    for (int t = 0; t < 16; t++) {
        int idx = tid + t * AT;                // 0..2047 float4s
        int r = idx >> 4, c4 = idx & 15;
        float4 v = *(const float4*)(qbase + (size_t)r * DD + c4 * 4);
        v.x = __uint_as_float(f2tf(v.x)); v.y = __uint_as_float(f2tf(v.y));
        v.z = __uint_as_float(f2tf(v.z)); v.w = __uint_as_float(f2tf(v.w));
        *(float4*)&sm[OFF_Q + r * LDK + c4 * 4] = v;
    }
    for (int i = tid; i < SLM; i += AT)
        sm[OFF_M + i] = -1e30f * (1.0f - maskp[(size_t)b * SLM + i]);

    float oc[2][8][4] = {};
    float l[4] = {0.f, 0.f, 0.f, 0.f};   // [mf*2 + half]
    int buf = 0;
    const int srcA = (lane & ~3) | (q >> 1);
    const int srcB = srcA + 2;
    const bool sel = (q & 1);

    for (int kt = 0; kt < SLM / BK; kt++) {
        asm volatile("cp.async.wait_group 0;\n" ::: "memory");
        __syncthreads();
        if (kt + 1 < SLM / BK) cpK(kt + 1, buf ^ 1);

        const float* sK = sm + (buf ? OFF_K1 : OFF_K0);

        // ---- S = Q K^T : 32 rows x 64 keys; B-frag shared across m-frags ----
        float sc[2][8][4] = {};
        #pragma unroll
        for (int kk = 0; kk < 8; kk++) {
            unsigned a[2][4];
            const float* qp = sm + OFF_Q + kk * 8 + q;
            #pragma unroll
            for (int mf = 0; mf < 2; mf++) {
                int r0 = qrow + mf * 16;
                a[mf][0] = __float_as_uint(qp[(r0 + g) * LDK]);
                a[mf][1] = __float_as_uint(qp[(r0 + g + 8) * LDK]);
                a[mf][2] = __float_as_uint(qp[(r0 + g) * LDK + 4]);
                a[mf][3] = __float_as_uint(qp[(r0 + g + 8) * LDK + 4]);
            }
            #pragma unroll
            for (int j = 0; j < 8; j++) {
                unsigned bb[2];
                bb[0] = __float_as_uint(sK[(j * 8 + g) * LDK + kk * 8 + q]);
                bb[1] = __float_as_uint(sK[(j * 8 + g) * LDK + kk * 8 + q + 4]);
                mma_tf32(sc[0][j], a[0], bb);
                mma_tf32(sc[1][j], a[1], bb);
            }
        }

        // ---- p = exp(s/8 + maskadd); row-sum partials (regs only) ----
        #pragma unroll
        for (int j = 0; j < 8; j++) {
            float2 mv = *(const float2*)&sm[OFF_M + kt * 64 + j * 8 + 2 * q];
            #pragma unroll
            for (int mf = 0; mf < 2; mf++) {
                float p0 = __expf(sc[mf][j][0] * 0.125f + mv.x);
                float p1 = __expf(sc[mf][j][1] * 0.125f + mv.y);
                float p2 = __expf(sc[mf][j][2] * 0.125f + mv.x);
                float p3 = __expf(sc[mf][j][3] * 0.125f + mv.y);
                l[mf * 2 + 0] += p0 + p1;
                l[mf * 2 + 1] += p2 + p3;
                sc[mf][j][0] = p0; sc[mf][j][1] = p1;
                sc[mf][j][2] = p2; sc[mf][j][3] = p3;
            }
        }

        // ---- O += P V : B-frag (V) loaded once per (j,nf), reused across m-frags ----
        #pragma unroll
        for (int j = 0; j < 8; j++) {
            unsigned bb[8][2];
            #pragma unroll
            for (int nf = 0; nf < 8; nf++) {
                bb[nf][0] = __float_as_uint(sK[(j * 8 + q) * LDK + nf * 8 + g]);
                bb[nf][1] = __float_as_uint(sK[(j * 8 + q + 4) * LDK + nf * 8 + g]);
            }
            #pragma unroll
            for (int mf = 0; mf < 2; mf++) {
                float t0 = __shfl_sync(0xffffffffu, sc[mf][j][0], srcA);
                float t1 = __shfl_sync(0xffffffffu, sc[mf][j][1], srcA);
                float t2 = __shfl_sync(0xffffffffu, sc[mf][j][2], srcA);
                float t3 = __shfl_sync(0xffffffffu, sc[mf][j][3], srcA);
                float u0 = __shfl_sync(0xffffffffu, sc[mf][j][0], srcB);
                float u1 = __shfl_sync(0xffffffffu, sc[mf][j][1], srcB);
                float u2 = __shfl_sync(0xffffffffu, sc[mf][j][2], srcB);
                float u3 = __shfl_sync(0xffffffffu, sc[mf][j][3], srcB);
                unsigned a[4];
                a[0] = __float_as_uint(sel ? t1 : t0);   // P(g,     8j+q)
                a[1] = __float_as_uint(sel ? t3 : t2);   // P(g+8,   8j+q)
                a[2] = __float_as_uint(sel ? u1 : u0);   // P(g,   8j+q+4)
                a[3] = __float_as_uint(sel ? u3 : u2);   // P(g+8, 8j+q+4)
                #pragma unroll
                for (int nf = 0; nf < 8; nf++)
                    mma_tf32(oc[mf][nf], a, bb[nf]);
            }
        }
        buf ^= 1;
    }

    // ---- complete row sums within the warp (cols live across q-lanes) ----
    #pragma unroll
    for (int i = 0; i < 4; i++) {
        l[i] += __shfl_xor_sync(0xffffffffu, l[i], 1);
        l[i] += __shfl_xor_sync(0xffffffffu, l[i], 2);
    }

    // ---- normalize, RN-round to tf32, write context ----
    #pragma unroll
    for (int mf = 0; mf < 2; mf++) {
        const float inv0 = 1.0f / l[mf * 2 + 0];   // row qrow+mf*16+g
        const float inv1 = 1.0f / l[mf * 2 + 1];   // row qrow+mf*16+g+8
        float* obase = g_ctx + ((size_t)(b * SLD + qt * BQ + qrow + mf * 16)) * DD + h * HS;
        #pragma unroll
        for (int nf = 0; nf < 8; nf++) {
            float2 v;
            v.x = __uint_as_float(f2tf(oc[mf][nf][0] * inv0));
            v.y = __uint_as_float(f2tf(oc[mf][nf][1] * inv0));
            *(float2*)&obase[(size_t)g * DD + nf * 8 + 2 * q] = v;
            v.x = __uint_as_float(f2tf(oc[mf][nf][2] * inv1));
            v.y = __uint_as_float(f2tf(oc[mf][nf][3] * inv1));
            *(float2*)&obase[(size_t)(g + 8) * DD + nf * 8 + 2 * q] = v;
        }
    }
}

// ==================== half GEMM (K=1024) + optional epilogue ====================
#define TM2 128
#define TN2 128
#define GBK 32
#define GLDS 36
#define GT2 256
#define STG_FLOATS ((TM2 + TN2) * GLDS)          // 9216 floats per stage
#define GEMM_SMEM_BYTES (3 * STG_FLOATS * 4)     // 110592 B

__device__ __forceinline__ float gated_act(float o) {
    o = fminf(fmaxf(o, -30.0f), 30.0f);
    float e = __expf(-o);
    return (1.0f - e) / (1.0f + e * e);   // == sigmoid(o)*tanh(o)
}

__global__ __launch_bounds__(GT2, 2)
void half_gemm_kernel(const float* __restrict__ src,
                      const float* __restrict__ wbase,
                      const float* __restrict__ bc,
                      float* __restrict__ accp,
                      float* __restrict__ outp,
                      int final_pass)
{
    extern __shared__ float sg[];
    const unsigned sbase = (unsigned)__cvta_generic_to_shared(sg);

    const int tid  = threadIdx.x;
    const int lane = tid & 31;
    const int warp = tid >> 5;
    const int g = lane >> 2;
    const int q = lane & 3;
    const int wm = warp >> 2;       // 0..1 -> rows wm*64
    const int wn = warp & 3;        // 0..3 -> cols wn*32
    const int n0 = blockIdx.x * TN2;
    const int m0 = blockIdx.y * TM2;

    auto stage = [&](int kb, int s) {
        const unsigned bx = sbase + (unsigned)(s * STG_FLOATS) * 4u;
        const unsigned bw = bx + (unsigned)(TM2 * GLDS) * 4u;
        #pragma unroll
        for (int t = 0; t < 4; t++) {
            int idx = tid + t * GT2;            // 0..1023
            int r = idx >> 3, c4 = idx & 7;     // row 0..127, float4 col 0..7
            cp16(bx + (unsigned)(r * GLDS + c4 * 4) * 4u,
                 src + (size_t)(m0 + r) * DD + kb + c4 * 4);
            cp16(bw + (unsigned)(r * GLDS + c4 * 4) * 4u,
                 wbase + (size_t)(n0 + r) * (2 * DD) + kb + c4 * 4);
        }
        asm volatile("cp.async.commit_group;" ::: "memory");
    };

    stage(0, 0);
    stage(GBK, 1);

    float acc[4][4][4] = {};

    for (int i = 0; i < DD / GBK; i++) {        // 32 iterations
        if (i + 1 < DD / GBK)
            asm volatile("cp.async.wait_group 1;" ::: "memory");
        else
            asm volatile("cp.async.wait_group 0;" ::: "memory");
        __syncthreads();
        if (i + 2 < DD / GBK) stage((i + 2) * GBK, (i + 2) % 3);

        const float* sX = sg + (i % 3) * STG_FLOATS;
        const float* sW = sX + TM2 * GLDS;

        #pragma unroll
        for (int kk = 0; kk < GBK; kk += 8) {
            unsigned a[4][4], bb[4][2];
            #pragma unroll
            for (int mi = 0; mi < 4; mi++) {
                const float* xp = sX + kk + q;
                int r0 = wm * 64 + mi * 16;
                a[mi][0] = __float_as_uint(xp[(r0 + g) * GLDS]);
                a[mi][1] = __float_as_uint(xp[(r0 + g + 8) * GLDS]);
                a[mi][2] = __float_as_uint(xp[(r0 + g) * GLDS + 4]);
                a[mi][3] = __float_as_uint(xp[(r0 + g + 8) * GLDS + 4]);
            }
            #pragma unroll
            for (int ni = 0; ni < 4; ni++) {
                int nw = wn * 32 + ni * 8;
                bb[ni][0] = __float_as_uint(sW[(nw + g) * GLDS + kk + q]);
                bb[ni][1] = __float_as_uint(sW[(nw + g) * GLDS + kk + q + 4]);
            }
            #pragma unroll
            for (int mi = 0; mi < 4; mi++)
                #pragma unroll
                for (int ni = 0; ni < 4; ni++)
                    mma_tf32(acc[mi][ni], a[mi], bb[ni]);
        }
    }

    if (final_pass) {
        #pragma unroll
        for (int ni = 0; ni < 4; ni++) {
            int col = n0 + wn * 32 + ni * 8 + 2 * q;
            float b0 = bc[col], b1 = bc[col + 1];
            #pragma unroll
            for (int mi = 0; mi < 4; mi++) {
                int row = m0 + wm * 64 + mi * 16 + g;
                float2 p0 = *(const float2*)&accp[(size_t)row * DD + col];
                float2 p1 = *(const float2*)&accp[(size_t)(row + 8) * DD + col];
                float2 v0, v1;
                v0.x = gated_act(acc[mi][ni][0] + p0.x + b0);
                v0.y = gated_act(acc[mi][ni][1] + p0.y + b1);
                v1.x = gated_act(acc[mi][ni][2] + p1.x + b0);
                v1.y = gated_act(acc[mi][ni][3] + p1.y + b1);
                *(float2*)&outp[(size_t)row * DD + col]       = v0;
                *(float2*)&outp[(size_t)(row + 8) * DD + col] = v1;
            }
        }
    } else {
        #pragma unroll
        for (int ni = 0; ni < 4; ni++) {
            int col = n0 + wn * 32 + ni * 8 + 2 * q;
            #pragma unroll
            for (int mi = 0; mi < 4; mi++) {
                int row = m0 + wm * 64 + mi * 16 + g;
                *(float2*)&accp[(size_t)row * DD + col] =
                    make_float2(acc[mi][ni][0], acc[mi][ni][1]);
                *(float2*)&accp[(size_t)(row + 8) * DD + col] =
                    make_float2(acc[mi][ni][2], acc[mi][ni][3]);
            }
        }
    }
}

extern "C" void kernel_launch(void* const* d_in, const int* in_sizes, int n_in,
                              void* d_out, int out_size)
{
    const float* inp  = (const float*)d_in[0];   // [8,1024,1024]
    const float* mem  = (const float*)d_in[1];   // [8,1024,1024]
    const float* mask = (const float*)d_in[2];   // [8,1024]
    const float* Wc   = (const float*)d_in[3];   // [1024,2048]
    const float* bc   = (const float*)d_in[4];   // [1024]
    float* outp = (float*)d_out;                 // [8,1024,1024]

    // one-time setup (first call = correctness run, NOT under graph capture)
    static cudaStream_t s2 = nullptr;
    static cudaEvent_t evFork = nullptr, evJoin = nullptr;
    if (!s2) {
        cudaStreamCreate(&s2);
        cudaEventCreateWithFlags(&evFork, cudaEventDisableTiming);
        cudaEventCreateWithFlags(&evJoin, cudaEventDisableTiming);
        cudaFuncSetAttribute(attn_kernel, cudaFuncAttributeMaxDynamicSharedMemorySize,
                             (int)(ATT_SMEM_FLOATS * sizeof(float)));
        cudaFuncSetAttribute(half_gemm_kernel, cudaFuncAttributeMaxDynamicSharedMemorySize,
                             GEMM_SMEM_BYTES);
    }

    float *xtf_p, *wtf_p, *ctx_p, *acc_p;
    cudaGetSymbolAddress((void**)&xtf_p, g_xtf);
    cudaGetSymbolAddress((void**)&wtf_p, g_wtf);
    cudaGetSymbolAddress((void**)&ctx_p, g_ctx);
    cudaGetSymbolAddress((void**)&acc_p, g_acc);

    // fork side stream from stream 0
    cudaEventRecord(evFork, 0);
    cudaStreamWaitEvent(s2, evFork, 0);

    // s2: round W and X, then X-half GEMM into g_acc (independent of attention)
    {
        int n4w = DD * 2 * DD / 4;       // 524288
        round_tf32_kernel<<<n4w / 256, 256, 0, s2>>>(Wc, wtf_p, n4w);
        int n4x = NB * SLD * DD / 4;     // 2097152
        round_tf32_kernel<<<n4x / 256, 256, 0, s2>>>(inp, xtf_p, n4x);
        dim3 ggrid(DD / TN2, (NB * SLD) / TM2);    // 8 x 64 = 512 blocks
        half_gemm_kernel<<<ggrid, GT2, GEMM_SMEM_BYTES, s2>>>(
            xtf_p, wtf_p, bc, acc_p, outp, 0);
    }
    cudaEventRecord(evJoin, s2);

    // stream 0: attention (concurrent with s2)
    dim3 agrid(SLD / BQ, HH, NB);              // 8 x 16 x 8 = 1024 blocks
    attn_kernel<<<agrid, AT, ATT_SMEM_FLOATS * sizeof(float)>>>(inp, mem, mask);

    // join, then C-half GEMM + epilogue
    cudaStreamWaitEvent(0, evJoin, 0);
    dim3 ggrid(DD / TN2, (NB * SLD) / TM2);
    half_gemm_kernel<<<ggrid, GT2, GEMM_SMEM_BYTES>>>(
        ctx_p, wtf_p + DD, bc, acc_p, outp, 1);
}

// round 10
// speedup vs baseline: 2.0088x; 1.0486x over previous
#include <cuda_runtime.h>
#include <cstdint>

#define NB  8
#define SLD 1024
#define SLM 1024
#define DD  1024
#define HH  16
#define HS  64

// Scratch: attention context (tf32-rounded), rounded X, rounded Wc
__device__ float g_ctx[(size_t)NB * SLD * DD];        // 32 MB
__device__ float g_xtf[(size_t)NB * SLD * DD];        // 32 MB
__device__ float g_wtf[(size_t)DD * 2 * DD];          // 8 MB

__device__ __forceinline__ void mma_tf32(float c[4], const unsigned a[4], const unsigned b[2]) {
    asm volatile(
        "mma.sync.aligned.m16n8k8.row.col.f32.tf32.tf32.f32 "
        "{%0,%1,%2,%3}, {%4,%5,%6,%7}, {%8,%9}, {%0,%1,%2,%3};\n"
        : "+f"(c[0]), "+f"(c[1]), "+f"(c[2]), "+f"(c[3])
        : "r"(a[0]), "r"(a[1]), "r"(a[2]), "r"(a[3]), "r"(b[0]), "r"(b[1]));
}

__device__ __forceinline__ void cp16(unsigned saddr, const float* gptr) {
    asm volatile("cp.async.cg.shared.global [%0], [%1], 16;\n" :: "r"(saddr), "l"(gptr));
}

__device__ __forceinline__ unsigned f2tf(float x) {
    unsigned u;
    asm("cvt.rna.tf32.f32 %0, %1;" : "=r"(u) : "f"(x));
    return u;
}

// ==================== prep: RN-round to tf32 in memory ====================
__global__ __launch_bounds__(256)
void round_tf32_kernel(const float* __restrict__ src, float* __restrict__ dst, int n4)
{
    int i = blockIdx.x * 256 + threadIdx.x;
    if (i < n4) {
        float4 v = ((const float4*)src)[i];
        v.x = __uint_as_float(f2tf(v.x));
        v.y = __uint_as_float(f2tf(v.y));
        v.z = __uint_as_float(f2tf(v.z));
        v.w = __uint_as_float(f2tf(v.w));
        ((float4*)dst)[i] = v;
    }
}

// ==================== flash attention: 32 rows/warp, shared B-fragments ====================
// (unchanged from R9: BQ=128, 4 warps, register-resident P, shfl layout fix)
#define BQ 128
#define BK 64
#define AT 128
#define LDK 68

#define OFF_K0   0
#define OFF_K1   (64*LDK)            // 4352
#define OFF_Q    (2*64*LDK)          // 8704, Q tile 128*68
#define OFF_M    (OFF_Q + BQ*LDK)    // 17408
#define ATT_SMEM_FLOATS (OFF_M + 1024)   // 18432 floats = 73728 B

__global__ __launch_bounds__(AT, 2)
void attn_kernel(const float* __restrict__ inp,
                 const float* __restrict__ mem,
                 const float* __restrict__ maskp)
{
    extern __shared__ float sm[];
    const unsigned sbase = (unsigned)__cvta_generic_to_shared(sm);

    const int tid  = threadIdx.x;
    const int lane = tid & 31;
    const int warp = tid >> 5;     // 0..3
    const int g = lane >> 2;       // 0..7
    const int q = lane & 3;        // 0..3
    const int qt = blockIdx.x, h = blockIdx.y, b = blockIdx.z;
    const int qrow = warp * 32;    // warp's first query row in tile

    const float* kbase = mem + (size_t)b * SLM * DD + h * HS;

    auto cpK = [&](int kt, int buf) {
        const int base = buf ? OFF_K1 : OFF_K0;
        #pragma unroll
        for (int t = 0; t < 8; t++) {
            int idx = tid + t * AT;            // 0..1023
            int r = idx >> 4, c4 = idx & 15;   // key row 0..63, float4 col
            unsigned sa = sbase + (unsigned)(base + r * LDK + c4 * 4) * 4u;
            cp16(sa, kbase + (size_t)(kt * BK + r) * DD + c4 * 4);
        }
        asm volatile("cp.async.commit_group;\n" ::: "memory");
    };
    cpK(0, 0);

    // stage Q tile [128][64] (RN-rounded) and additive mask row
    const float* qbase = inp + ((size_t)(b * SLD + qt * BQ)) * DD + h * HS;
    #pragma unroll
    for (int t = 0; t < 16; t++) {
        int idx = tid + t * AT;                // 0..2047 float4s
        int r = idx >> 4, c4 = idx & 15;
        float4 v = *(const float4*)(qbase + (size_t)r * DD + c4 * 4);
        v.x = __uint_as_float(f2tf(v.x)); v.y = __uint_as_float(f2tf(v.y));
        v.z = __uint_as_float(f2tf(v.z)); v.w = __uint_as_float(f2tf(v.w));
        *(float4*)&sm[OFF_Q + r * LDK + c4 * 4] = v;
    }
    for (int i = tid; i < SLM; i += AT)
        sm[OFF_M + i] = -1e30f * (1.0f - maskp[(size_t)b * SLM + i]);

    float oc[2][8][4] = {};
    float l[4] = {0.f, 0.f, 0.f, 0.f};   // [mf*2 + half]
    int buf = 0;
    const int srcA = (lane & ~3) | (q >> 1);
    const int srcB = srcA + 2;
    const bool sel = (q & 1);

    for (int kt = 0; kt < SLM / BK; kt++) {
        asm volatile("cp.async.wait_group 0;\n" ::: "memory");
        __syncthreads();
        if (kt + 1 < SLM / BK) cpK(kt + 1, buf ^ 1);

        const float* sK = sm + (buf ? OFF_K1 : OFF_K0);

        // ---- S = Q K^T : 32 rows x 64 keys; B-frag shared across m-frags ----
        float sc[2][8][4] = {};
        #pragma unroll
        for (int kk = 0; kk < 8; kk++) {
            unsigned a[2][4];
            const float* qp = sm + OFF_Q + kk * 8 + q;
            #pragma unroll
            for (int mf = 0; mf < 2; mf++) {
                int r0 = qrow + mf * 16;
                a[mf][0] = __float_as_uint(qp[(r0 + g) * LDK]);
                a[mf][1] = __float_as_uint(qp[(r0 + g + 8) * LDK]);
                a[mf][2] = __float_as_uint(qp[(r0 + g) * LDK + 4]);
                a[mf][3] = __float_as_uint(qp[(r0 + g + 8) * LDK + 4]);
            }
            #pragma unroll
            for (int j = 0; j < 8; j++) {
                unsigned bb[2];
                bb[0] = __float_as_uint(sK[(j * 8 + g) * LDK + kk * 8 + q]);
                bb[1] = __float_as_uint(sK[(j * 8 + g) * LDK + kk * 8 + q + 4]);
                mma_tf32(sc[0][j], a[0], bb);
                mma_tf32(sc[1][j], a[1], bb);
            }
        }

        // ---- p = exp(s/8 + maskadd); row-sum partials (regs only) ----
        #pragma unroll
        for (int j = 0; j < 8; j++) {
            float2 mv = *(const float2*)&sm[OFF_M + kt * 64 + j * 8 + 2 * q];
            #pragma unroll
            for (int mf = 0; mf < 2; mf++) {
                float p0 = __expf(sc[mf][j][0] * 0.125f + mv.x);
                float p1 = __expf(sc[mf][j][1] * 0.125f + mv.y);
                float p2 = __expf(sc[mf][j][2] * 0.125f + mv.x);
                float p3 = __expf(sc[mf][j][3] * 0.125f + mv.y);
                l[mf * 2 + 0] += p0 + p1;
                l[mf * 2 + 1] += p2 + p3;
                sc[mf][j][0] = p0; sc[mf][j][1] = p1;
                sc[mf][j][2] = p2; sc[mf][j][3] = p3;
            }
        }

        // ---- O += P V : B-frag (V) loaded once per (j,nf), reused across m-frags ----
        #pragma unroll
        for (int j = 0; j < 8; j++) {
            unsigned bb[8][2];
            #pragma unroll
            for (int nf = 0; nf < 8; nf++) {
                bb[nf][0] = __float_as_uint(sK[(j * 8 + q) * LDK + nf * 8 + g]);
                bb[nf][1] = __float_as_uint(sK[(j * 8 + q + 4) * LDK + nf * 8 + g]);
            }
            #pragma unroll
            for (int mf = 0; mf < 2; mf++) {
                float t0 = __shfl_sync(0xffffffffu, sc[mf][j][0], srcA);
                float t1 = __shfl_sync(0xffffffffu, sc[mf][j][1], srcA);
                float t2 = __shfl_sync(0xffffffffu, sc[mf][j][2], srcA);
                float t3 = __shfl_sync(0xffffffffu, sc[mf][j][3], srcA);
                float u0 = __shfl_sync(0xffffffffu, sc[mf][j][0], srcB);
                float u1 = __shfl_sync(0xffffffffu, sc[mf][j][1], srcB);
                float u2 = __shfl_sync(0xffffffffu, sc[mf][j][2], srcB);
                float u3 = __shfl_sync(0xffffffffu, sc[mf][j][3], srcB);
                unsigned a[4];
                a[0] = __float_as_uint(sel ? t1 : t0);   // P(g,     8j+q)
                a[1] = __float_as_uint(sel ? t3 : t2);   // P(g+8,   8j+q)
                a[2] = __float_as_uint(sel ? u1 : u0);   // P(g,   8j+q+4)
                a[3] = __float_as_uint(sel ? u3 : u2);   // P(g+8, 8j+q+4)
                #pragma unroll
                for (int nf = 0; nf < 8; nf++)
                    mma_tf32(oc[mf][nf], a, bb[nf]);
            }
        }
        buf ^= 1;
    }

    // ---- complete row sums within the warp (cols live across q-lanes) ----
    #pragma unroll
    for (int i = 0; i < 4; i++) {
        l[i] += __shfl_xor_sync(0xffffffffu, l[i], 1);
        l[i] += __shfl_xor_sync(0xffffffffu, l[i], 2);
    }

    // ---- normalize, RN-round to tf32, write context ----
    #pragma unroll
    for (int mf = 0; mf < 2; mf++) {
        const float inv0 = 1.0f / l[mf * 2 + 0];   // row qrow+mf*16+g
        const float inv1 = 1.0f / l[mf * 2 + 1];   // row qrow+mf*16+g+8
        float* obase = g_ctx + ((size_t)(b * SLD + qt * BQ + qrow + mf * 16)) * DD + h * HS;
        #pragma unroll
        for (int nf = 0; nf < 8; nf++) {
            float2 v;
            v.x = __uint_as_float(f2tf(oc[mf][nf][0] * inv0));
            v.y = __uint_as_float(f2tf(oc[mf][nf][1] * inv0));
            *(float2*)&obase[(size_t)g * DD + nf * 8 + 2 * q] = v;
            v.x = __uint_as_float(f2tf(oc[mf][nf][2] * inv1));
            v.y = __uint_as_float(f2tf(oc[mf][nf][3] * inv1));
            *(float2*)&obase[(size_t)(g + 8) * DD + nf * 8 + 2 * q] = v;
        }
    }
}

// ==================== fused projection GEMM (K=2048) + gated activation ====================
// out[m][n] = act( sum_k X[m][k] Wc[n][k] + bc[n] ), X = [g_xtf | g_ctx]
// CTA 128x128, 128 threads, 4 warps of 64x64 (1.0 mma per LDS.32), 2-stage ring.
#define TM2 128
#define TN2 128
#define GBK 32
#define GLDS 36
#define GT2 128
#define STG_FLOATS ((TM2 + TN2) * GLDS)          // 9216 floats per stage
#define GEMM_SMEM_BYTES (2 * STG_FLOATS * 4)     // 73728 B

__device__ __forceinline__ float gated_act(float o) {
    o = fminf(fmaxf(o, -30.0f), 30.0f);
    float e = __expf(-o);
    return (1.0f - e) / (1.0f + e * e);   // == sigmoid(o)*tanh(o)
}

__global__ __launch_bounds__(GT2, 2)
void out_gemm_kernel(const float* __restrict__ bc, float* __restrict__ outp)
{
    extern __shared__ float sg[];
    const unsigned sbase = (unsigned)__cvta_generic_to_shared(sg);

    const int tid  = threadIdx.x;
    const int lane = tid & 31;
    const int warp = tid >> 5;      // 0..3
    const int g = lane >> 2;
    const int q = lane & 3;
    const int wm = warp >> 1;       // 0..1 -> rows wm*64
    const int wn = warp & 1;        // 0..1 -> cols wn*64
    const int n0 = blockIdx.x * TN2;
    const int m0 = blockIdx.y * TM2;

    auto stage = [&](int kb, int s) {
        const float* src = (kb < DD) ? g_xtf : g_ctx;
        const int koff = kb & (DD - 1);
        const unsigned bx = sbase + (unsigned)(s * STG_FLOATS) * 4u;
        const unsigned bw = bx + (unsigned)(TM2 * GLDS) * 4u;
        #pragma unroll
        for (int t = 0; t < 8; t++) {
            int idx = tid + t * GT2;            // 0..1023
            int r = idx >> 3, c4 = idx & 7;     // row 0..127, float4 col 0..7
            cp16(bx + (unsigned)(r * GLDS + c4 * 4) * 4u,
                 src + (size_t)(m0 + r) * DD + koff + c4 * 4);
            cp16(bw + (unsigned)(r * GLDS + c4 * 4) * 4u,
                 g_wtf + (size_t)(n0 + r) * (2 * DD) + kb + c4 * 4);
        }
        asm volatile("cp.async.commit_group;" ::: "memory");
    };

    stage(0, 0);

    float acc[4][8][4] = {};

    for (int i = 0; i < 2 * DD / GBK; i++) {    // 64 iterations
        asm volatile("cp.async.wait_group 0;" ::: "memory");
        __syncthreads();
        if (i + 1 < 2 * DD / GBK) stage((i + 1) * GBK, (i + 1) & 1);

        const float* sX = sg + (i & 1) * STG_FLOATS;
        const float* sW = sX + TM2 * GLDS;

        #pragma unroll
        for (int kk = 0; kk < GBK; kk += 8) {
            unsigned a[4][4], bb[8][2];
            #pragma unroll
            for (int mi = 0; mi < 4; mi++) {
                const float* xp = sX + kk + q;
                int r0 = wm * 64 + mi * 16;
                a[mi][0] = __float_as_uint(xp[(r0 + g) * GLDS]);
                a[mi][1] = __float_as_uint(xp[(r0 + g + 8) * GLDS]);
                a[mi][2] = __float_as_uint(xp[(r0 + g) * GLDS + 4]);
                a[mi][3] = __float_as_uint(xp[(r0 + g + 8) * GLDS + 4]);
            }
            #pragma unroll
            for (int ni = 0; ni < 8; ni++) {
                int nw = wn * 64 + ni * 8;
                bb[ni][0] = __float_as_uint(sW[(nw + g) * GLDS + kk + q]);
                bb[ni][1] = __float_as_uint(sW[(nw + g) * GLDS + kk + q + 4]);
            }
            #pragma unroll
            for (int mi = 0; mi < 4; mi++)
                #pragma unroll
                for (int ni = 0; ni < 8; ni++)
                    mma_tf32(acc[mi][ni], a[mi], bb[ni]);
        }
    }

    // ---- epilogue: bias + sigmoid*tanh, direct to global ----
    #pragma unroll
    for (int ni = 0; ni < 8; ni++) {
        int col = n0 + wn * 64 + ni * 8 + 2 * q;
        float b0 = bc[col], b1 = bc[col + 1];
        #pragma unroll
        for (int mi = 0; mi < 4; mi++) {
            int row = m0 + wm * 64 + mi * 16 + g;
            float2 v0, v1;
            v0.x = gated_act(acc[mi][ni][0] + b0);
            v0.y = gated_act(acc[mi][ni][1] + b1);
            v1.x = gated_act(acc[mi][ni][2] + b0);
            v1.y = gated_act(acc[mi][ni][3] + b1);
            *(float2*)&outp[(size_t)row * DD + col]       = v0;
            *(float2*)&outp[(size_t)(row + 8) * DD + col] = v1;
        }
    }
}

extern "C" void kernel_launch(void* const* d_in, const int* in_sizes, int n_in,
                              void* d_out, int out_size)
{
    const float* inp  = (const float*)d_in[0];   // [8,1024,1024]
    const float* mem  = (const float*)d_in[1];   // [8,1024,1024]
    const float* mask = (const float*)d_in[2];   // [8,1024]
    const float* Wc   = (const float*)d_in[3];   // [1024,2048]
    const float* bc   = (const float*)d_in[4];   // [1024]
    float* outp = (float*)d_out;                 // [8,1024,1024]

    // one-time setup (first call = correctness run, NOT under graph capture)
    static cudaStream_t s2 = nullptr;
    static cudaEvent_t evFork = nullptr, evJoin = nullptr;
    if (!s2) {
        cudaStreamCreate(&s2);
        cudaEventCreateWithFlags(&evFork, cudaEventDisableTiming);
        cudaEventCreateWithFlags(&evJoin, cudaEventDisableTiming);
        cudaFuncSetAttribute(attn_kernel, cudaFuncAttributeMaxDynamicSharedMemorySize,
                             (int)(ATT_SMEM_FLOATS * sizeof(float)));
        cudaFuncSetAttribute(out_gemm_kernel, cudaFuncAttributeMaxDynamicSharedMemorySize,
                             GEMM_SMEM_BYTES);
    }

    float *xtf_p, *wtf_p;
    cudaGetSymbolAddress((void**)&xtf_p, g_xtf);
    cudaGetSymbolAddress((void**)&wtf_p, g_wtf);

    // fork: tf32 rounding on s2 (overlaps attention's head)
    cudaEventRecord(evFork, 0);
    cudaStreamWaitEvent(s2, evFork, 0);
    {
        int n4w = DD * 2 * DD / 4;       // 524288
        round_tf32_kernel<<<n4w / 256, 256, 0, s2>>>(Wc, wtf_p, n4w);
        int n4x = NB * SLD * DD / 4;     // 2097152
        round_tf32_kernel<<<n4x / 256, 256, 0, s2>>>(inp, xtf_p, n4x);
    }
    cudaEventRecord(evJoin, s2);

    // stream 0: attention
    dim3 agrid(SLD / BQ, HH, NB);              // 8 x 16 x 8 = 1024 blocks
    attn_kernel<<<agrid, AT, ATT_SMEM_FLOATS * sizeof(float)>>>(inp, mem, mask);

    // join, then fused projection GEMM + epilogue
    cudaStreamWaitEvent(0, evJoin, 0);
    dim3 ggrid(DD / TN2, (NB * SLD) / TM2);    // 8 x 64 = 512 blocks
    out_gemm_kernel<<<ggrid, GT2, GEMM_SMEM_BYTES>>>(bc, outp);
}

// round 11
// speedup vs baseline: 2.6198x; 1.3042x over previous
#include <cuda_runtime.h>
#include <cuda_fp16.h>
#include <cstdint>

#define NB  8
#define SLD 1024
#define SLM 1024
#define DD  1024
#define HH  16
#define HS  64

// Scratch: ctx (fp16), X (fp16), Wc (fp16)
__device__ __half g_ctxh[(size_t)NB * SLD * DD];      // 16 MB
__device__ __half g_xh[(size_t)NB * SLD * DD];        // 16 MB
__device__ __half g_wh[(size_t)DD * 2 * DD];          // 4 MB

__device__ __forceinline__ void mma_tf32(float c[4], const unsigned a[4], const unsigned b[2]) {
    asm volatile(
        "mma.sync.aligned.m16n8k8.row.col.f32.tf32.tf32.f32 "
        "{%0,%1,%2,%3}, {%4,%5,%6,%7}, {%8,%9}, {%0,%1,%2,%3};\n"
        : "+f"(c[0]), "+f"(c[1]), "+f"(c[2]), "+f"(c[3])
        : "r"(a[0]), "r"(a[1]), "r"(a[2]), "r"(a[3]), "r"(b[0]), "r"(b[1]));
}

__device__ __forceinline__ void mma_f16(float c[4], const unsigned a[4], const unsigned b[2]) {
    asm volatile(
        "mma.sync.aligned.m16n8k16.row.col.f32.f16.f16.f32 "
        "{%0,%1,%2,%3}, {%4,%5,%6,%7}, {%8,%9}, {%0,%1,%2,%3};\n"
        : "+f"(c[0]), "+f"(c[1]), "+f"(c[2]), "+f"(c[3])
        : "r"(a[0]), "r"(a[1]), "r"(a[2]), "r"(a[3]), "r"(b[0]), "r"(b[1]));
}

__device__ __forceinline__ void cp16(unsigned saddr, const void* gptr) {
    asm volatile("cp.async.cg.shared.global [%0], [%1], 16;\n" :: "r"(saddr), "l"(gptr));
}

__device__ __forceinline__ unsigned f2tf(float x) {
    unsigned u;
    asm("cvt.rna.tf32.f32 %0, %1;" : "=r"(u) : "f"(x));
    return u;
}

// ==================== prep: RN-round fp32 -> fp16 in memory ====================
__global__ __launch_bounds__(256)
void round_half_kernel(const float* __restrict__ src, __half* __restrict__ dst, int n4)
{
    int i = blockIdx.x * 256 + threadIdx.x;
    if (i < n4) {
        float4 v = ((const float4*)src)[i];
        __half2 h0 = __floats2half2_rn(v.x, v.y);
        __half2 h1 = __floats2half2_rn(v.z, v.w);
        uint2 o;
        o.x = *(unsigned*)&h0;
        o.y = *(unsigned*)&h1;
        *(uint2*)&dst[(size_t)i * 4] = o;
    }
}

// ==================== flash attention (R9 core; epilogue writes fp16 ctx) ====================
#define BQ 128
#define BK 64
#define AT 128
#define LDK 68

#define OFF_K0   0
#define OFF_K1   (64*LDK)            // 4352
#define OFF_Q    (2*64*LDK)          // 8704, Q tile 128*68
#define OFF_M    (OFF_Q + BQ*LDK)    // 17408
#define ATT_SMEM_FLOATS (OFF_M + 1024)   // 18432 floats = 73728 B

__global__ __launch_bounds__(AT, 2)
void attn_kernel(const float* __restrict__ inp,
                 const float* __restrict__ mem,
                 const float* __restrict__ maskp)
{
    extern __shared__ float sm[];
    const unsigned sbase = (unsigned)__cvta_generic_to_shared(sm);

    const int tid  = threadIdx.x;
    const int lane = tid & 31;
    const int warp = tid >> 5;     // 0..3
    const int g = lane >> 2;       // 0..7
    const int q = lane & 3;        // 0..3
    const int qt = blockIdx.x, h = blockIdx.y, b = blockIdx.z;
    const int qrow = warp * 32;    // warp's first query row in tile

    const float* kbase = mem + (size_t)b * SLM * DD + h * HS;

    auto cpK = [&](int kt, int buf) {
        const int base = buf ? OFF_K1 : OFF_K0;
        #pragma unroll
        for (int t = 0; t < 8; t++) {
            int idx = tid + t * AT;            // 0..1023
            int r = idx >> 4, c4 = idx & 15;   // key row 0..63, float4 col
            unsigned sa = sbase + (unsigned)(base + r * LDK + c4 * 4) * 4u;
            cp16(sa, kbase + (size_t)(kt * BK + r) * DD + c4 * 4);
        }
        asm volatile("cp.async.commit_group;\n" ::: "memory");
    };
    cpK(0, 0);

    // stage Q tile [128][64] (RN-rounded tf32) and additive mask row
    const float* qbase = inp + ((size_t)(b * SLD + qt * BQ)) * DD + h * HS;
    #pragma unroll
    for (int t = 0; t < 16; t++) {
        int idx = tid + t * AT;                // 0..2047 float4s
        int r = idx >> 4, c4 = idx & 15;
        float4 v = *(const float4*)(qbase + (size_t)r * DD + c4 * 4);
        v.x = __uint_as_float(f2tf(v.x)); v.y = __uint_as_float(f2tf(v.y));
        v.z = __uint_as_float(f2tf(v.z)); v.w = __uint_as_float(f2tf(v.w));
        *(float4*)&sm[OFF_Q + r * LDK + c4 * 4] = v;
    }
    for (int i = tid; i < SLM; i += AT)
        sm[OFF_M + i] = -1e30f * (1.0f - maskp[(size_t)b * SLM + i]);

    float oc[2][8][4] = {};
    float l[4] = {0.f, 0.f, 0.f, 0.f};   // [mf*2 + half]
    int buf = 0;
    const int srcA = (lane & ~3) | (q >> 1);
    const int srcB = srcA + 2;
    const bool sel = (q & 1);

    for (int kt = 0; kt < SLM / BK; kt++) {
        asm volatile("cp.async.wait_group 0;\n" ::: "memory");
        __syncthreads();
        if (kt + 1 < SLM / BK) cpK(kt + 1, buf ^ 1);

        const float* sK = sm + (buf ? OFF_K1 : OFF_K0);

        // ---- S = Q K^T : 32 rows x 64 keys; B-frag shared across m-frags ----
        float sc[2][8][4] = {};
        #pragma unroll
        for (int kk = 0; kk < 8; kk++) {
            unsigned a[2][4];
            const float* qp = sm + OFF_Q + kk * 8 + q;
            #pragma unroll
            for (int mf = 0; mf < 2; mf++) {
                int r0 = qrow + mf * 16;
                a[mf][0] = __float_as_uint(qp[(r0 + g) * LDK]);
                a[mf][1] = __float_as_uint(qp[(r0 + g + 8) * LDK]);
                a[mf][2] = __float_as_uint(qp[(r0 + g) * LDK + 4]);
                a[mf][3] = __float_as_uint(qp[(r0 + g + 8) * LDK + 4]);
            }
            #pragma unroll
            for (int j = 0; j < 8; j++) {
                unsigned bb[2];
                bb[0] = __float_as_uint(sK[(j * 8 + g) * LDK + kk * 8 + q]);
                bb[1] = __float_as_uint(sK[(j * 8 + g) * LDK + kk * 8 + q + 4]);
                mma_tf32(sc[0][j], a[0], bb);
                mma_tf32(sc[1][j], a[1], bb);
            }
        }

        // ---- p = exp(s/8 + maskadd); row-sum partials (regs only) ----
        #pragma unroll
        for (int j = 0; j < 8; j++) {
            float2 mv = *(const float2*)&sm[OFF_M + kt * 64 + j * 8 + 2 * q];
            #pragma unroll
            for (int mf = 0; mf < 2; mf++) {
                float p0 = __expf(sc[mf][j][0] * 0.125f + mv.x);
                float p1 = __expf(sc[mf][j][1] * 0.125f + mv.y);
                float p2 = __expf(sc[mf][j][2] * 0.125f + mv.x);
                float p3 = __expf(sc[mf][j][3] * 0.125f + mv.y);
                l[mf * 2 + 0] += p0 + p1;
                l[mf * 2 + 1] += p2 + p3;
                sc[mf][j][0] = p0; sc[mf][j][1] = p1;
                sc[mf][j][2] = p2; sc[mf][j][3] = p3;
            }
        }

        // ---- O += P V : B-frag (V) loaded once per (j,nf), reused across m-frags ----
        #pragma unroll
        for (int j = 0; j < 8; j++) {
            unsigned bb[8][2];
            #pragma unroll
            for (int nf = 0; nf < 8; nf++) {
                bb[nf][0] = __float_as_uint(sK[(j * 8 + q) * LDK + nf * 8 + g]);
                bb[nf][1] = __float_as_uint(sK[(j * 8 + q + 4) * LDK + nf * 8 + g]);
            }
            #pragma unroll
            for (int mf = 0; mf < 2; mf++) {
                float t0 = __shfl_sync(0xffffffffu, sc[mf][j][0], srcA);
                float t1 = __shfl_sync(0xffffffffu, sc[mf][j][1], srcA);
                float t2 = __shfl_sync(0xffffffffu, sc[mf][j][2], srcA);
                float t3 = __shfl_sync(0xffffffffu, sc[mf][j][3], srcA);
                float u0 = __shfl_sync(0xffffffffu, sc[mf][j][0], srcB);
                float u1 = __shfl_sync(0xffffffffu, sc[mf][j][1], srcB);
                float u2 = __shfl_sync(0xffffffffu, sc[mf][j][2], srcB);
                float u3 = __shfl_sync(0xffffffffu, sc[mf][j][3], srcB);
                unsigned a[4];
                a[0] = __float_as_uint(sel ? t1 : t0);   // P(g,     8j+q)
                a[1] = __float_as_uint(sel ? t3 : t2);   // P(g+8,   8j+q)
                a[2] = __float_as_uint(sel ? u1 : u0);   // P(g,   8j+q+4)
                a[3] = __float_as_uint(sel ? u3 : u2);   // P(g+8, 8j+q+4)
                #pragma unroll
                for (int nf = 0; nf < 8; nf++)
                    mma_tf32(oc[mf][nf], a, bb[nf]);
            }
        }
        buf ^= 1;
    }

    // ---- complete row sums within the warp ----
    #pragma unroll
    for (int i = 0; i < 4; i++) {
        l[i] += __shfl_xor_sync(0xffffffffu, l[i], 1);
        l[i] += __shfl_xor_sync(0xffffffffu, l[i], 2);
    }

    // ---- normalize, round to fp16, write context ----
    #pragma unroll
    for (int mf = 0; mf < 2; mf++) {
        const float inv0 = 1.0f / l[mf * 2 + 0];   // row qrow+mf*16+g
        const float inv1 = 1.0f / l[mf * 2 + 1];   // row qrow+mf*16+g+8
        __half* obase = g_ctxh + ((size_t)(b * SLD + qt * BQ + qrow + mf * 16)) * DD + h * HS;
        #pragma unroll
        for (int nf = 0; nf < 8; nf++) {
            __half2 v;
            v = __floats2half2_rn(oc[mf][nf][0] * inv0, oc[mf][nf][1] * inv0);
            *(__half2*)&obase[(size_t)g * DD + nf * 8 + 2 * q] = v;
            v = __floats2half2_rn(oc[mf][nf][2] * inv1, oc[mf][nf][3] * inv1);
            *(__half2*)&obase[(size_t)(g + 8) * DD + nf * 8 + 2 * q] = v;
        }
    }
}

// ==================== fused projection GEMM (K=2048, fp16) + gated activation ====================
// out[m][n] = act( sum_k X[m][k] Wc[n][k] + bc[n] ), X = [g_xh | g_ctxh], fp16 x fp16 -> fp32
// CTA 128x128, 128 threads, 4 warps of 64x64, mma.m16n8k16, 3-stage cp.async ring.
#define TM2 128
#define TN2 128
#define GBK 32                     // k halves per stage
#define GLH 40                     // smem row stride in halves (80B, conflict-free)
#define GT2 128
#define STG_BYTES ((TM2 + TN2) * GLH * 2)        // 20480 B per stage
#define GEMM_SMEM_BYTES (3 * STG_BYTES)          // 61440 B

__device__ __forceinline__ float gated_act(float o) {
    o = fminf(fmaxf(o, -30.0f), 30.0f);
    float e = __expf(-o);
    return (1.0f - e) / (1.0f + e * e);   // == sigmoid(o)*tanh(o)
}

__global__ __launch_bounds__(GT2, 2)
void out_gemm_kernel(const float* __restrict__ bc, float* __restrict__ outp)
{
    extern __shared__ __align__(16) char sgb[];
    const unsigned sbase = (unsigned)__cvta_generic_to_shared(sgb);

    const int tid  = threadIdx.x;
    const int lane = tid & 31;
    const int warp = tid >> 5;      // 0..3
    const int g = lane >> 2;
    const int q = lane & 3;
    const int wm = warp >> 1;       // 0..1 -> rows wm*64
    const int wn = warp & 1;        // 0..1 -> cols wn*64
    const int n0 = blockIdx.x * TN2;
    const int m0 = blockIdx.y * TM2;

    // stage 32 k-halves (64B) per row for X[128 rows] and W[128 rows]
    auto stage = [&](int kb, int s) {
        const __half* src = (kb < DD) ? g_xh : g_ctxh;
        const int koff = kb & (DD - 1);
        const unsigned bx = sbase + (unsigned)(s * STG_BYTES);
        const unsigned bw = bx + (unsigned)(TM2 * GLH * 2);
        #pragma unroll
        for (int t = 0; t < 4; t++) {
            int idx = tid + t * GT2;            // 0..511
            int r = idx >> 2, c = idx & 3;      // row 0..127, 16B chunk 0..3
            cp16(bx + (unsigned)(r * GLH * 2 + c * 16),
                 src + (size_t)(m0 + r) * DD + koff + c * 8);
            cp16(bw + (unsigned)(r * GLH * 2 + c * 16),
                 g_wh + (size_t)(n0 + r) * (2 * DD) + kb + c * 8);
        }
        asm volatile("cp.async.commit_group;" ::: "memory");
    };

    stage(0, 0);
    stage(GBK, 1);

    float acc[4][8][4] = {};

    for (int i = 0; i < 2 * DD / GBK; i++) {    // 64 iterations
        if (i + 1 < 2 * DD / GBK)
            asm volatile("cp.async.wait_group 1;" ::: "memory");
        else
            asm volatile("cp.async.wait_group 0;" ::: "memory");
        __syncthreads();
        if (i + 2 < 2 * DD / GBK) stage((i + 2) * GBK, (i + 2) % 3);

        const __half* sX = (const __half*)(sgb + (i % 3) * STG_BYTES);
        const __half* sW = sX + TM2 * GLH;

        #pragma unroll
        for (int kk = 0; kk < GBK; kk += 16) {
            unsigned a[4][4], bb[8][2];
            #pragma unroll
            for (int mi = 0; mi < 4; mi++) {
                int r0 = wm * 64 + mi * 16;
                const __half* xp = sX + kk + 2 * q;
                a[mi][0] = *(const unsigned*)&xp[(r0 + g) * GLH];
                a[mi][1] = *(const unsigned*)&xp[(r0 + g + 8) * GLH];
                a[mi][2] = *(const unsigned*)&xp[(r0 + g) * GLH + 8];
                a[mi][3] = *(const unsigned*)&xp[(r0 + g + 8) * GLH + 8];
            }
            #pragma unroll
            for (int ni = 0; ni < 8; ni++) {
                int nw = wn * 64 + ni * 8;
                bb[ni][0] = *(const unsigned*)&sW[(nw + g) * GLH + kk + 2 * q];
                bb[ni][1] = *(const unsigned*)&sW[(nw + g) * GLH + kk + 2 * q + 8];
            }
            #pragma unroll
            for (int mi = 0; mi < 4; mi++)
                #pragma unroll
                for (int ni = 0; ni < 8; ni++)
                    mma_f16(acc[mi][ni], a[mi], bb[ni]);
        }
    }

    // ---- epilogue: bias + sigmoid*tanh, direct to global ----
    #pragma unroll
    for (int ni = 0; ni < 8; ni++) {
        int col = n0 + wn * 64 + ni * 8 + 2 * q;
        float b0 = bc[col], b1 = bc[col + 1];
        #pragma unroll
        for (int mi = 0; mi < 4; mi++) {
            int row = m0 + wm * 64 + mi * 16 + g;
            float2 v0, v1;
            v0.x = gated_act(acc[mi][ni][0] + b0);
            v0.y = gated_act(acc[mi][ni][1] + b1);
            v1.x = gated_act(acc[mi][ni][2] + b0);
            v1.y = gated_act(acc[mi][ni][3] + b1);
            *(float2*)&outp[(size_t)row * DD + col]       = v0;
            *(float2*)&outp[(size_t)(row + 8) * DD + col] = v1;
        }
    }
}

extern "C" void kernel_launch(void* const* d_in, const int* in_sizes, int n_in,
                              void* d_out, int out_size)
{
    const float* inp  = (const float*)d_in[0];   // [8,1024,1024]
    const float* mem  = (const float*)d_in[1];   // [8,1024,1024]
    const float* mask = (const float*)d_in[2];   // [8,1024]
    const float* Wc   = (const float*)d_in[3];   // [1024,2048]
    const float* bc   = (const float*)d_in[4];   // [1024]
    float* outp = (float*)d_out;                 // [8,1024,1024]

    // one-time setup (first call = correctness run, NOT under graph capture)
    static cudaStream_t s2 = nullptr;
    static cudaEvent_t evFork = nullptr, evJoin = nullptr;
    if (!s2) {
        cudaStreamCreate(&s2);
        cudaEventCreateWithFlags(&evFork, cudaEventDisableTiming);
        cudaEventCreateWithFlags(&evJoin, cudaEventDisableTiming);
        cudaFuncSetAttribute(attn_kernel, cudaFuncAttributeMaxDynamicSharedMemorySize,
                             (int)(ATT_SMEM_FLOATS * sizeof(float)));
        cudaFuncSetAttribute(out_gemm_kernel, cudaFuncAttributeMaxDynamicSharedMemorySize,
                             GEMM_SMEM_BYTES);
    }

    __half *xh_p, *wh_p;
    cudaGetSymbolAddress((void**)&xh_p, g_xh);
    cudaGetSymbolAddress((void**)&wh_p, g_wh);

    // fork: fp16 rounding on s2 (overlaps attention's head)
    cudaEventRecord(evFork, 0);
    cudaStreamWaitEvent(s2, evFork, 0);
    {
        int n4w = DD * 2 * DD / 4;       // 524288
        round_half_kernel<<<n4w / 256, 256, 0, s2>>>(Wc, wh_p, n4w);
        int n4x = NB * SLD * DD / 4;     // 2097152
        round_half_kernel<<<n4x / 256, 256, 0, s2>>>(inp, xh_p, n4x);
    }
    cudaEventRecord(evJoin, s2);

    // stream 0: attention
    dim3 agrid(SLD / BQ, HH, NB);              // 8 x 16 x 8 = 1024 blocks
    attn_kernel<<<agrid, AT, ATT_SMEM_FLOATS * sizeof(float)>>>(inp, mem, mask);

    // join, then fused projection GEMM + epilogue
    cudaStreamWaitEvent(0, evJoin, 0);
    dim3 ggrid(DD / TN2, (NB * SLD) / TM2);    // 8 x 64 = 512 blocks
    out_gemm_kernel<<<ggrid, GT2, GEMM_SMEM_BYTES>>>(bc, outp);
}

// round 12
// speedup vs baseline: 3.1502x; 1.2024x over previous
#include <cuda_runtime.h>
#include <cuda_fp16.h>
#include <cstdint>

#define NB  8
#define SLD 1024
#define SLM 1024
#define DD  1024
#define HH  16
#define HS  64

// Scratch: ctx (fp16), X (fp16), Wc (fp16), mem (fp16)
__device__ __half g_ctxh[(size_t)NB * SLD * DD];      // 16 MB
__device__ __half g_xh[(size_t)NB * SLD * DD];        // 16 MB
__device__ __half g_wh[(size_t)DD * 2 * DD];          // 4 MB
__device__ __half g_memh[(size_t)NB * SLM * DD];      // 16 MB

__device__ __forceinline__ void mma_f16(float c[4], const unsigned a[4], const unsigned b[2]) {
    asm volatile(
        "mma.sync.aligned.m16n8k16.row.col.f32.f16.f16.f32 "
        "{%0,%1,%2,%3}, {%4,%5,%6,%7}, {%8,%9}, {%0,%1,%2,%3};\n"
        : "+f"(c[0]), "+f"(c[1]), "+f"(c[2]), "+f"(c[3])
        : "r"(a[0]), "r"(a[1]), "r"(a[2]), "r"(a[3]), "r"(b[0]), "r"(b[1]));
}

__device__ __forceinline__ void ldsm4(unsigned r[4], unsigned addr) {
    asm volatile("ldmatrix.sync.aligned.m8n8.x4.shared.b16 {%0,%1,%2,%3}, [%4];"
        : "=r"(r[0]), "=r"(r[1]), "=r"(r[2]), "=r"(r[3]) : "r"(addr));
}

__device__ __forceinline__ void ldsm4t(unsigned r[4], unsigned addr) {
    asm volatile("ldmatrix.sync.aligned.m8n8.x4.trans.shared.b16 {%0,%1,%2,%3}, [%4];"
        : "=r"(r[0]), "=r"(r[1]), "=r"(r[2]), "=r"(r[3]) : "r"(addr));
}

__device__ __forceinline__ void cp16(unsigned saddr, const void* gptr) {
    asm volatile("cp.async.cg.shared.global [%0], [%1], 16;\n" :: "r"(saddr), "l"(gptr));
}

__device__ __forceinline__ unsigned packh2(float x, float y) {
    __half2 h = __floats2half2_rn(x, y);
    return *(unsigned*)&h;
}

// ==================== prep: RN-round fp32 -> fp16 in memory ====================
__global__ __launch_bounds__(256)
void round_half_kernel(const float* __restrict__ src, __half* __restrict__ dst, int n4)
{
    int i = blockIdx.x * 256 + threadIdx.x;
    if (i < n4) {
        float4 v = ((const float4*)src)[i];
        __half2 h0 = __floats2half2_rn(v.x, v.y);
        __half2 h1 = __floats2half2_rn(v.z, v.w);
        uint2 o;
        o.x = *(unsigned*)&h0;
        o.y = *(unsigned*)&h1;
        *(uint2*)&dst[(size_t)i * 4] = o;
    }
}

// ==================== flash attention: fp16 mma + ldmatrix ====================
// BQ=128, 4 warps, 32 rows/warp; P converted acc->A-frag by pure register packs.
#define BQ 128
#define BK 64
#define AT 128
#define LDHB 144                      // smem row stride bytes (72 halves)

#define OFF_Q   0                     // 128*144 = 18432 B
#define OFF_K0  18432                 // 64*144 = 9216 B
#define OFF_K1  27648                 // 9216 B
#define OFF_MB  36864                 // mask fp32, 4096 B
#define ATT_SMEM_BYTES (OFF_MB + 4096)   // 40960 B

__global__ __launch_bounds__(AT, 2)
void attn_kernel(const float* __restrict__ inp,
                 const float* __restrict__ maskp)
{
    extern __shared__ __align__(16) char smb[];
    const unsigned sbase = (unsigned)__cvta_generic_to_shared(smb);
    float* smf = (float*)(smb + OFF_MB);

    const int tid  = threadIdx.x;
    const int lane = tid & 31;
    const int warp = tid >> 5;     // 0..3
    const int g = lane >> 2;       // 0..7
    const int q = lane & 3;        // 0..3
    const int quad = lane >> 3;    // 0..3
    const int rl = lane & 7;       // 0..7
    const int qt = blockIdx.x, h = blockIdx.y, b = blockIdx.z;
    const int qrow = warp * 32;    // warp's first query row in tile

    const __half* kbase = g_memh + (size_t)b * SLM * DD + h * HS;

    auto cpK = [&](int kt, int buf) {
        const unsigned base = sbase + (buf ? OFF_K1 : OFF_K0);
        #pragma unroll
        for (int t = 0; t < 4; t++) {
            int idx = tid + t * AT;            // 0..511
            int r = idx >> 3, c = idx & 7;     // key row 0..63, 16B chunk 0..7
            cp16(base + (unsigned)(r * LDHB + c * 16),
                 kbase + (size_t)(kt * BK + r) * DD + c * 8);
        }
        asm volatile("cp.async.commit_group;\n" ::: "memory");
    };
    cpK(0, 0);

    // stage Q tile [128][64] fp32 -> fp16 and additive mask row
    const float* qbase = inp + ((size_t)(b * SLD + qt * BQ)) * DD + h * HS;
    #pragma unroll
    for (int t = 0; t < 16; t++) {
        int idx = tid + t * AT;                // 0..2047 float4s
        int r = idx >> 4, c4 = idx & 15;
        float4 v = *(const float4*)(qbase + (size_t)r * DD + c4 * 4);
        uint2 o;
        o.x = packh2(v.x, v.y);
        o.y = packh2(v.z, v.w);
        *(uint2*)(smb + OFF_Q + r * LDHB + c4 * 8) = o;
    }
    for (int i = tid; i < SLM; i += AT)
        smf[i] = -1e30f * (1.0f - maskp[(size_t)b * SLM + i]);

    float oc[2][8][4] = {};
    float l[4] = {0.f, 0.f, 0.f, 0.f};   // [mf*2 + half]
    int buf = 0;

    for (int kt = 0; kt < SLM / BK; kt++) {
        asm volatile("cp.async.wait_group 0;\n" ::: "memory");
        __syncthreads();
        if (kt + 1 < SLM / BK) cpK(kt + 1, buf ^ 1);

        const unsigned sK = sbase + (buf ? OFF_K1 : OFF_K0);

        // ---- S = Q K^T : 32 rows x 64 keys, fp16 k16 steps ----
        float sc[2][8][4] = {};
        #pragma unroll
        for (int kk = 0; kk < 4; kk++) {
            unsigned a[2][4];
            #pragma unroll
            for (int mf = 0; mf < 2; mf++) {
                // A mats: quad0: rows r0..7 klow; q1: rows+8 klow; q2: rows khigh; q3: rows+8 khigh
                int row = qrow + mf * 16 + (quad & 1) * 8 + rl;
                int colh = kk * 16 + (quad >> 1) * 8;
                ldsm4(a[mf], sbase + OFF_Q + (unsigned)(row * LDHB + colh * 2));
            }
            unsigned bb[8][2];
            #pragma unroll
            for (int j2 = 0; j2 < 8; j2 += 2) {
                // B mats: q0: keys j2*8 klow; q1: j2 khigh; q2: j2+1 klow; q3: j2+1 khigh
                int row = (j2 + (quad >> 1)) * 8 + rl;
                int colh = kk * 16 + (quad & 1) * 8;
                unsigned bt[4];
                ldsm4(bt, sK + (unsigned)(row * LDHB + colh * 2));
                bb[j2][0] = bt[0]; bb[j2][1] = bt[1];
                bb[j2 + 1][0] = bt[2]; bb[j2 + 1][1] = bt[3];
            }
            #pragma unroll
            for (int mf = 0; mf < 2; mf++)
                #pragma unroll
                for (int j = 0; j < 8; j++)
                    mma_f16(sc[mf][j], a[mf], bb[j]);
        }

        // ---- p = exp(s/8 + maskadd); row-sum partials ----
        #pragma unroll
        for (int j = 0; j < 8; j++) {
            float2 mv = *(const float2*)&smf[kt * 64 + j * 8 + 2 * q];
            #pragma unroll
            for (int mf = 0; mf < 2; mf++) {
                float p0 = __expf(sc[mf][j][0] * 0.125f + mv.x);
                float p1 = __expf(sc[mf][j][1] * 0.125f + mv.y);
                float p2 = __expf(sc[mf][j][2] * 0.125f + mv.x);
                float p3 = __expf(sc[mf][j][3] * 0.125f + mv.y);
                l[mf * 2 + 0] += p0 + p1;
                l[mf * 2 + 1] += p2 + p3;
                sc[mf][j][0] = p0; sc[mf][j][1] = p1;
                sc[mf][j][2] = p2; sc[mf][j][3] = p3;
            }
        }

        // ---- O += P V : A-frags by register pack; B via ldmatrix.trans on K tile ----
        #pragma unroll
        for (int t = 0; t < 4; t++) {
            unsigned aP[2][4];
            #pragma unroll
            for (int mf = 0; mf < 2; mf++) {
                aP[mf][0] = packh2(sc[mf][2 * t][0],     sc[mf][2 * t][1]);
                aP[mf][1] = packh2(sc[mf][2 * t][2],     sc[mf][2 * t][3]);
                aP[mf][2] = packh2(sc[mf][2 * t + 1][0], sc[mf][2 * t + 1][1]);
                aP[mf][3] = packh2(sc[mf][2 * t + 1][2], sc[mf][2 * t + 1][3]);
            }
            unsigned bb[8][2];
            #pragma unroll
            for (int nf2 = 0; nf2 < 8; nf2 += 2) {
                // trans B mats: q0: keys 16t..+8 col nf2*8; q1: keys+8; q2/q3: col (nf2+1)*8
                int row = 16 * t + (quad & 1) * 8 + rl;
                int colh = (nf2 + (quad >> 1)) * 8;
                unsigned bt[4];
                ldsm4t(bt, sK + (unsigned)(row * LDHB + colh * 2));
                bb[nf2][0] = bt[0]; bb[nf2][1] = bt[1];
                bb[nf2 + 1][0] = bt[2]; bb[nf2 + 1][1] = bt[3];
            }
            #pragma unroll
            for (int mf = 0; mf < 2; mf++)
                #pragma unroll
                for (int nf = 0; nf < 8; nf++)
                    mma_f16(oc[mf][nf], aP[mf], bb[nf]);
        }
        buf ^= 1;
    }

    // ---- complete row sums within the warp ----
    #pragma unroll
    for (int i = 0; i < 4; i++) {
        l[i] += __shfl_xor_sync(0xffffffffu, l[i], 1);
        l[i] += __shfl_xor_sync(0xffffffffu, l[i], 2);
    }

    // ---- normalize, round to fp16, write context ----
    #pragma unroll
    for (int mf = 0; mf < 2; mf++) {
        const float inv0 = 1.0f / l[mf * 2 + 0];   // row qrow+mf*16+g
        const float inv1 = 1.0f / l[mf * 2 + 1];   // row qrow+mf*16+g+8
        __half* obase = g_ctxh + ((size_t)(b * SLD + qt * BQ + qrow + mf * 16)) * DD + h * HS;
        #pragma unroll
        for (int nf = 0; nf < 8; nf++) {
            __half2 v;
            v = __floats2half2_rn(oc[mf][nf][0] * inv0, oc[mf][nf][1] * inv0);
            *(__half2*)&obase[(size_t)g * DD + nf * 8 + 2 * q] = v;
            v = __floats2half2_rn(oc[mf][nf][2] * inv1, oc[mf][nf][3] * inv1);
            *(__half2*)&obase[(size_t)(g + 8) * DD + nf * 8 + 2 * q] = v;
        }
    }
}

// ==================== fused projection GEMM (K=2048, fp16) + gated activation ====================
// (unchanged from R11)
#define TM2 128
#define TN2 128
#define GBK 32
#define GLH 40
#define GT2 128
#define STG_BYTES ((TM2 + TN2) * GLH * 2)        // 20480 B per stage
#define GEMM_SMEM_BYTES (3 * STG_BYTES)          // 61440 B

__device__ __forceinline__ float gated_act(float o) {
    o = fminf(fmaxf(o, -30.0f), 30.0f);
    float e = __expf(-o);
    return (1.0f - e) / (1.0f + e * e);   // == sigmoid(o)*tanh(o)
}

__global__ __launch_bounds__(GT2, 2)
void out_gemm_kernel(const float* __restrict__ bc, float* __restrict__ outp)
{
    extern __shared__ __align__(16) char sgb[];
    const unsigned sbase = (unsigned)__cvta_generic_to_shared(sgb);

    const int tid  = threadIdx.x;
    const int lane = tid & 31;
    const int warp = tid >> 5;      // 0..3
    const int g = lane >> 2;
    const int q = lane & 3;
    const int wm = warp >> 1;       // 0..1 -> rows wm*64
    const int wn = warp & 1;        // 0..1 -> cols wn*64
    const int n0 = blockIdx.x * TN2;
    const int m0 = blockIdx.y * TM2;

    auto stage = [&](int kb, int s) {
        const __half* src = (kb < DD) ? g_xh : g_ctxh;
        const int koff = kb & (DD - 1);
        const unsigned bx = sbase + (unsigned)(s * STG_BYTES);
        const unsigned bw = bx + (unsigned)(TM2 * GLH * 2);
        #pragma unroll
        for (int t = 0; t < 4; t++) {
            int idx = tid + t * GT2;            // 0..511
            int r = idx >> 2, c = idx & 3;      // row 0..127, 16B chunk 0..3
            cp16(bx + (unsigned)(r * GLH * 2 + c * 16),
                 src + (size_t)(m0 + r) * DD + koff + c * 8);
            cp16(bw + (unsigned)(r * GLH * 2 + c * 16),
                 g_wh + (size_t)(n0 + r) * (2 * DD) + kb + c * 8);
        }
        asm volatile("cp.async.commit_group;" ::: "memory");
    };

    stage(0, 0);
    stage(GBK, 1);

    float acc[4][8][4] = {};

    for (int i = 0; i < 2 * DD / GBK; i++) {    // 64 iterations
        if (i + 1 < 2 * DD / GBK)
            asm volatile("cp.async.wait_group 1;" ::: "memory");
        else
            asm volatile("cp.async.wait_group 0;" ::: "memory");
        __syncthreads();
        if (i + 2 < 2 * DD / GBK) stage((i + 2) * GBK, (i + 2) % 3);

        const __half* sX = (const __half*)(sgb + (i % 3) * STG_BYTES);
        const __half* sW = sX + TM2 * GLH;

        #pragma unroll
        for (int kk = 0; kk < GBK; kk += 16) {
            unsigned a[4][4], bb[8][2];
            #pragma unroll
            for (int mi = 0; mi < 4; mi++) {
                int r0 = wm * 64 + mi * 16;
                const __half* xp = sX + kk + 2 * q;
                a[mi][0] = *(const unsigned*)&xp[(r0 + g) * GLH];
                a[mi][1] = *(const unsigned*)&xp[(r0 + g + 8) * GLH];
                a[mi][2] = *(const unsigned*)&xp[(r0 + g) * GLH + 8];
                a[mi][3] = *(const unsigned*)&xp[(r0 + g + 8) * GLH + 8];
            }
            #pragma unroll
            for (int ni = 0; ni < 8; ni++) {
                int nw = wn * 64 + ni * 8;
                bb[ni][0] = *(const unsigned*)&sW[(nw + g) * GLH + kk + 2 * q];
                bb[ni][1] = *(const unsigned*)&sW[(nw + g) * GLH + kk + 2 * q + 8];
            }
            #pragma unroll
            for (int mi = 0; mi < 4; mi++)
                #pragma unroll
                for (int ni = 0; ni < 8; ni++)
                    mma_f16(acc[mi][ni], a[mi], bb[ni]);
        }
    }

    // ---- epilogue: bias + sigmoid*tanh, direct to global ----
    #pragma unroll
    for (int ni = 0; ni < 8; ni++) {
        int col = n0 + wn * 64 + ni * 8 + 2 * q;
        float b0 = bc[col], b1 = bc[col + 1];
        #pragma unroll
        for (int mi = 0; mi < 4; mi++) {
            int row = m0 + wm * 64 + mi * 16 + g;
            float2 v0, v1;
            v0.x = gated_act(acc[mi][ni][0] + b0);
            v0.y = gated_act(acc[mi][ni][1] + b1);
            v1.x = gated_act(acc[mi][ni][2] + b0);
            v1.y = gated_act(acc[mi][ni][3] + b1);
            *(float2*)&outp[(size_t)row * DD + col]       = v0;
            *(float2*)&outp[(size_t)(row + 8) * DD + col] = v1;
        }
    }
}

extern "C" void kernel_launch(void* const* d_in, const int* in_sizes, int n_in,
                              void* d_out, int out_size)
{
    const float* inp  = (const float*)d_in[0];   // [8,1024,1024]
    const float* mem  = (const float*)d_in[1];   // [8,1024,1024]
    const float* mask = (const float*)d_in[2];   // [8,1024]
    const float* Wc   = (const float*)d_in[3];   // [1024,2048]
    const float* bc   = (const float*)d_in[4];   // [1024]
    float* outp = (float*)d_out;                 // [8,1024,1024]

    // one-time setup (first call = correctness run, NOT under graph capture)
    static cudaStream_t s2 = nullptr;
    static cudaEvent_t evFork = nullptr, evJoin = nullptr;
    if (!s2) {
        cudaStreamCreate(&s2);
        cudaEventCreateWithFlags(&evFork, cudaEventDisableTiming);
        cudaEventCreateWithFlags(&evJoin, cudaEventDisableTiming);
        cudaFuncSetAttribute(attn_kernel, cudaFuncAttributeMaxDynamicSharedMemorySize,
                             ATT_SMEM_BYTES);
        cudaFuncSetAttribute(out_gemm_kernel, cudaFuncAttributeMaxDynamicSharedMemorySize,
                             GEMM_SMEM_BYTES);
    }

    __half *xh_p, *wh_p, *memh_p;
    cudaGetSymbolAddress((void**)&xh_p, g_xh);
    cudaGetSymbolAddress((void**)&wh_p, g_wh);
    cudaGetSymbolAddress((void**)&memh_p, g_memh);

    // fork: W/X fp16 rounding on s2 (overlaps attention)
    cudaEventRecord(evFork, 0);
    cudaStreamWaitEvent(s2, evFork, 0);
    {
        int n4w = DD * 2 * DD / 4;       // 524288
        round_half_kernel<<<n4w / 256, 256, 0, s2>>>(Wc, wh_p, n4w);
        int n4x = NB * SLD * DD / 4;     // 2097152
        round_half_kernel<<<n4x / 256, 256, 0, s2>>>(inp, xh_p, n4x);
    }
    cudaEventRecord(evJoin, s2);

    // stream 0: mem -> fp16, then attention
    {
        int n4m = NB * SLM * DD / 4;     // 2097152
        round_half_kernel<<<n4m / 256, 256>>>(mem, memh_p, n4m);
    }
    dim3 agrid(SLD / BQ, HH, NB);              // 8 x 16 x 8 = 1024 blocks
    attn_kernel<<<agrid, AT, ATT_SMEM_BYTES>>>(inp, mask);

    // join, then fused projection GEMM + epilogue
    cudaStreamWaitEvent(0, evJoin, 0);
    dim3 ggrid(DD / TN2, (NB * SLD) / TM2);    // 8 x 64 = 512 blocks
    out_gemm_kernel<<<ggrid, GT2, GEMM_SMEM_BYTES>>>(bc, outp);
}

// round 13
// speedup vs baseline: 3.6331x; 1.1533x over previous
#include <cuda_runtime.h>
#include <cuda_fp16.h>
#include <cstdint>

#define NB  8
#define SLD 1024
#define SLM 1024
#define DD  1024
#define HH  16
#define HS  64

// Scratch: ctx (fp16), X (fp16), Wc (fp16), mem (fp16)
__device__ __half g_ctxh[(size_t)NB * SLD * DD];      // 16 MB
__device__ __half g_xh[(size_t)NB * SLD * DD];        // 16 MB
__device__ __half g_wh[(size_t)DD * 2 * DD];          // 4 MB
__device__ __half g_memh[(size_t)NB * SLM * DD];      // 16 MB

#define QSCALE 0.1803368801111204f   // 0.125 * log2(e)
#define L2E    1.4426950408889634f

__device__ __forceinline__ void mma_f16(float c[4], const unsigned a[4], const unsigned b[2]) {
    asm volatile(
        "mma.sync.aligned.m16n8k16.row.col.f32.f16.f16.f32 "
        "{%0,%1,%2,%3}, {%4,%5,%6,%7}, {%8,%9}, {%0,%1,%2,%3};\n"
        : "+f"(c[0]), "+f"(c[1]), "+f"(c[2]), "+f"(c[3])
        : "r"(a[0]), "r"(a[1]), "r"(a[2]), "r"(a[3]), "r"(b[0]), "r"(b[1]));
}

__device__ __forceinline__ void ldsm4(unsigned r[4], unsigned addr) {
    asm volatile("ldmatrix.sync.aligned.m8n8.x4.shared.b16 {%0,%1,%2,%3}, [%4];"
        : "=r"(r[0]), "=r"(r[1]), "=r"(r[2]), "=r"(r[3]) : "r"(addr));
}

__device__ __forceinline__ void ldsm4t(unsigned r[4], unsigned addr) {
    asm volatile("ldmatrix.sync.aligned.m8n8.x4.trans.shared.b16 {%0,%1,%2,%3}, [%4];"
        : "=r"(r[0]), "=r"(r[1]), "=r"(r[2]), "=r"(r[3]) : "r"(addr));
}

__device__ __forceinline__ void cp16(unsigned saddr, const void* gptr) {
    asm volatile("cp.async.cg.shared.global [%0], [%1], 16;\n" :: "r"(saddr), "l"(gptr));
}

__device__ __forceinline__ unsigned packh2(float x, float y) {
    __half2 h = __floats2half2_rn(x, y);
    return *(unsigned*)&h;
}

__device__ __forceinline__ float ex2f(float x) {
    float y;
    asm("ex2.approx.ftz.f32 %0, %1;" : "=f"(y) : "f"(x));
    return y;
}

// ==================== prep: RN-round fp32 -> fp16 in memory ====================
__global__ __launch_bounds__(256)
void round_half_kernel(const float* __restrict__ src, __half* __restrict__ dst, int n4)
{
    int i = blockIdx.x * 256 + threadIdx.x;
    if (i < n4) {
        float4 v = ((const float4*)src)[i];
        __half2 h0 = __floats2half2_rn(v.x, v.y);
        __half2 h1 = __floats2half2_rn(v.z, v.w);
        uint2 o;
        o.x = *(unsigned*)&h0;
        o.y = *(unsigned*)&h1;
        *(uint2*)&dst[(size_t)i * 4] = o;
    }
}

// ==================== flash attention: fp16 mma + ldmatrix + folded ex2 ====================
#define BQ 128
#define BK 64
#define AT 128
#define LDHB 144                      // smem row stride bytes (72 halves)

#define OFF_Q   0                     // 128*144 = 18432 B
#define OFF_K0  18432                 // 64*144 = 9216 B
#define OFF_K1  27648                 // 9216 B
#define OFF_MB  36864                 // mask fp32, 4096 B
#define ATT_SMEM_BYTES (OFF_MB + 4096)   // 40960 B

__global__ __launch_bounds__(AT, 2)
void attn_kernel(const float* __restrict__ inp,
                 const float* __restrict__ maskp)
{
    extern __shared__ __align__(16) char smb[];
    const unsigned sbase = (unsigned)__cvta_generic_to_shared(smb);
    float* smf = (float*)(smb + OFF_MB);

    const int tid  = threadIdx.x;
    const int lane = tid & 31;
    const int warp = tid >> 5;     // 0..3
    const int g = lane >> 2;       // 0..7
    const int q = lane & 3;        // 0..3
    const int quad = lane >> 3;    // 0..3
    const int rl = lane & 7;       // 0..7
    const int qt = blockIdx.x, h = blockIdx.y, b = blockIdx.z;
    const int qrow = warp * 32;    // warp's first query row in tile

    const __half* kbase = g_memh + (size_t)b * SLM * DD + h * HS;

    auto cpK = [&](int kt, int buf) {
        const unsigned base = sbase + (buf ? OFF_K1 : OFF_K0);
        #pragma unroll
        for (int t = 0; t < 4; t++) {
            int idx = tid + t * AT;            // 0..511
            int r = idx >> 3, c = idx & 7;     // key row 0..63, 16B chunk 0..7
            cp16(base + (unsigned)(r * LDHB + c * 16),
                 kbase + (size_t)(kt * BK + r) * DD + c * 8);
        }
        asm volatile("cp.async.commit_group;\n" ::: "memory");
    };
    cpK(0, 0);

    // stage Q tile [128][64] fp32*QSCALE -> fp16; mask pre-scaled by log2(e)
    const float* qbase = inp + ((size_t)(b * SLD + qt * BQ)) * DD + h * HS;
    #pragma unroll
    for (int t = 0; t < 16; t++) {
        int idx = tid + t * AT;                // 0..2047 float4s
        int r = idx >> 4, c4 = idx & 15;
        float4 v = *(const float4*)(qbase + (size_t)r * DD + c4 * 4);
        uint2 o;
        o.x = packh2(v.x * QSCALE, v.y * QSCALE);
        o.y = packh2(v.z * QSCALE, v.w * QSCALE);
        *(uint2*)(smb + OFF_Q + r * LDHB + c4 * 8) = o;
    }
    for (int i = tid; i < SLM; i += AT)
        smf[i] = (-1e30f * L2E) * (1.0f - maskp[(size_t)b * SLM + i]);

    float oc[2][8][4] = {};
    float l[4] = {0.f, 0.f, 0.f, 0.f};   // [mf*2 + half]
    int buf = 0;

    for (int kt = 0; kt < SLM / BK; kt++) {
        asm volatile("cp.async.wait_group 0;\n" ::: "memory");
        __syncthreads();
        if (kt + 1 < SLM / BK) cpK(kt + 1, buf ^ 1);

        const unsigned sK = sbase + (buf ? OFF_K1 : OFF_K0);

        // ---- S' = (Q*qscale) K^T : 32 rows x 64 keys ----
        float sc[2][8][4] = {};
        #pragma unroll
        for (int kk = 0; kk < 4; kk++) {
            unsigned a[2][4];
            #pragma unroll
            for (int mf = 0; mf < 2; mf++) {
                int row = qrow + mf * 16 + (quad & 1) * 8 + rl;
                int colh = kk * 16 + (quad >> 1) * 8;
                ldsm4(a[mf], sbase + OFF_Q + (unsigned)(row * LDHB + colh * 2));
            }
            unsigned bb[8][2];
            #pragma unroll
            for (int j2 = 0; j2 < 8; j2 += 2) {
                int row = (j2 + (quad >> 1)) * 8 + rl;
                int colh = kk * 16 + (quad & 1) * 8;
                unsigned bt[4];
                ldsm4(bt, sK + (unsigned)(row * LDHB + colh * 2));
                bb[j2][0] = bt[0]; bb[j2][1] = bt[1];
                bb[j2 + 1][0] = bt[2]; bb[j2 + 1][1] = bt[3];
            }
            #pragma unroll
            for (int mf = 0; mf < 2; mf++)
                #pragma unroll
                for (int j = 0; j < 8; j++)
                    mma_f16(sc[mf][j], a[mf], bb[j]);
        }

        // ---- p = ex2(s' + m'); row-sum partials ----
        #pragma unroll
        for (int j = 0; j < 8; j++) {
            float2 mv = *(const float2*)&smf[kt * 64 + j * 8 + 2 * q];
            #pragma unroll
            for (int mf = 0; mf < 2; mf++) {
                float p0 = ex2f(sc[mf][j][0] + mv.x);
                float p1 = ex2f(sc[mf][j][1] + mv.y);
                float p2 = ex2f(sc[mf][j][2] + mv.x);
                float p3 = ex2f(sc[mf][j][3] + mv.y);
                l[mf * 2 + 0] += p0 + p1;
                l[mf * 2 + 1] += p2 + p3;
                sc[mf][j][0] = p0; sc[mf][j][1] = p1;
                sc[mf][j][2] = p2; sc[mf][j][3] = p3;
            }
        }

        // ---- O += P V : A-frags by register pack; B via ldmatrix.trans ----
        #pragma unroll
        for (int t = 0; t < 4; t++) {
            unsigned aP[2][4];
            #pragma unroll
            for (int mf = 0; mf < 2; mf++) {
                aP[mf][0] = packh2(sc[mf][2 * t][0],     sc[mf][2 * t][1]);
                aP[mf][1] = packh2(sc[mf][2 * t][2],     sc[mf][2 * t][3]);
                aP[mf][2] = packh2(sc[mf][2 * t + 1][0], sc[mf][2 * t + 1][1]);
                aP[mf][3] = packh2(sc[mf][2 * t + 1][2], sc[mf][2 * t + 1][3]);
            }
            unsigned bb[8][2];
            #pragma unroll
            for (int nf2 = 0; nf2 < 8; nf2 += 2) {
                int row = 16 * t + (quad & 1) * 8 + rl;
                int colh = (nf2 + (quad >> 1)) * 8;
                unsigned bt[4];
                ldsm4t(bt, sK + (unsigned)(row * LDHB + colh * 2));
                bb[nf2][0] = bt[0]; bb[nf2][1] = bt[1];
                bb[nf2 + 1][0] = bt[2]; bb[nf2 + 1][1] = bt[3];
            }
            #pragma unroll
            for (int mf = 0; mf < 2; mf++)
                #pragma unroll
                for (int nf = 0; nf < 8; nf++)
                    mma_f16(oc[mf][nf], aP[mf], bb[nf]);
        }
        buf ^= 1;
    }

    // ---- complete row sums within the warp ----
    #pragma unroll
    for (int i = 0; i < 4; i++) {
        l[i] += __shfl_xor_sync(0xffffffffu, l[i], 1);
        l[i] += __shfl_xor_sync(0xffffffffu, l[i], 2);
    }

    // ---- normalize, round to fp16, write context ----
    #pragma unroll
    for (int mf = 0; mf < 2; mf++) {
        const float inv0 = 1.0f / l[mf * 2 + 0];
        const float inv1 = 1.0f / l[mf * 2 + 1];
        __half* obase = g_ctxh + ((size_t)(b * SLD + qt * BQ + qrow + mf * 16)) * DD + h * HS;
        #pragma unroll
        for (int nf = 0; nf < 8; nf++) {
            __half2 v;
            v = __floats2half2_rn(oc[mf][nf][0] * inv0, oc[mf][nf][1] * inv0);
            *(__half2*)&obase[(size_t)g * DD + nf * 8 + 2 * q] = v;
            v = __floats2half2_rn(oc[mf][nf][2] * inv1, oc[mf][nf][3] * inv1);
            *(__half2*)&obase[(size_t)(g + 8) * DD + nf * 8 + 2 * q] = v;
        }
    }
}

// ==================== fused projection GEMM (K=2048, fp16, ldmatrix) ====================
#define TM2 128
#define TN2 128
#define GBK 32
#define GLH 40
#define GT2 128
#define STG_BYTES ((TM2 + TN2) * GLH * 2)        // 20480 B per stage
#define GEMM_SMEM_BYTES (3 * STG_BYTES)          // 61440 B

__device__ __forceinline__ float gated_act(float o) {
    o = fminf(fmaxf(o, -30.0f), 30.0f);
    float e = __expf(-o);
    return (1.0f - e) / (1.0f + e * e);   // == sigmoid(o)*tanh(o)
}

__global__ __launch_bounds__(GT2, 2)
void out_gemm_kernel(const float* __restrict__ bc, float* __restrict__ outp)
{
    extern __shared__ __align__(16) char sgb[];
    const unsigned sbase = (unsigned)__cvta_generic_to_shared(sgb);

    const int tid  = threadIdx.x;
    const int lane = tid & 31;
    const int warp = tid >> 5;      // 0..3
    const int g = lane >> 2;
    const int q = lane & 3;
    const int quad = lane >> 3;    // 0..3
    const int rl = lane & 7;       // 0..7
    const int wm = warp >> 1;       // 0..1 -> rows wm*64
    const int wn = warp & 1;        // 0..1 -> cols wn*64
    const int n0 = blockIdx.x * TN2;
    const int m0 = blockIdx.y * TM2;

    auto stage = [&](int kb, int s) {
        const __half* src = (kb < DD) ? g_xh : g_ctxh;
        const int koff = kb & (DD - 1);
        const unsigned bx = sbase + (unsigned)(s * STG_BYTES);
        const unsigned bw = bx + (unsigned)(TM2 * GLH * 2);
        #pragma unroll
        for (int t = 0; t < 4; t++) {
            int idx = tid + t * GT2;            // 0..511
            int r = idx >> 2, c = idx & 3;      // row 0..127, 16B chunk 0..3
            cp16(bx + (unsigned)(r * GLH * 2 + c * 16),
                 src + (size_t)(m0 + r) * DD + koff + c * 8);
            cp16(bw + (unsigned)(r * GLH * 2 + c * 16),
                 g_wh + (size_t)(n0 + r) * (2 * DD) + kb + c * 8);
        }
        asm volatile("cp.async.commit_group;" ::: "memory");
    };

    stage(0, 0);
    stage(GBK, 1);

    float acc[4][8][4] = {};

    for (int i = 0; i < 2 * DD / GBK; i++) {    // 64 iterations
        if (i + 1 < 2 * DD / GBK)
            asm volatile("cp.async.wait_group 1;" ::: "memory");
        else
            asm volatile("cp.async.wait_group 0;" ::: "memory");
        __syncthreads();
        if (i + 2 < 2 * DD / GBK) stage((i + 2) * GBK, (i + 2) % 3);

        const unsigned sX = sbase + (unsigned)((i % 3) * STG_BYTES);
        const unsigned sW = sX + (unsigned)(TM2 * GLH * 2);

        #pragma unroll
        for (int kk = 0; kk < GBK; kk += 16) {
            unsigned a[4][4], bb[8][2];
            #pragma unroll
            for (int mi = 0; mi < 4; mi++) {
                int row = wm * 64 + mi * 16 + (quad & 1) * 8 + rl;
                int colh = kk + (quad >> 1) * 8;
                ldsm4(a[mi], sX + (unsigned)(row * GLH * 2 + colh * 2));
            }
            #pragma unroll
            for (int ni2 = 0; ni2 < 8; ni2 += 2) {
                int row = wn * 64 + (ni2 + (quad >> 1)) * 8 + rl;
                int colh = kk + (quad & 1) * 8;
                unsigned bt[4];
                ldsm4(bt, sW + (unsigned)(row * GLH * 2 + colh * 2));
                bb[ni2][0] = bt[0]; bb[ni2][1] = bt[1];
                bb[ni2 + 1][0] = bt[2]; bb[ni2 + 1][1] = bt[3];
            }
            #pragma unroll
            for (int mi = 0; mi < 4; mi++)
                #pragma unroll
                for (int ni = 0; ni < 8; ni++)
                    mma_f16(acc[mi][ni], a[mi], bb[ni]);
        }
    }

    // ---- epilogue: bias + sigmoid*tanh, direct to global ----
    #pragma unroll
    for (int ni = 0; ni < 8; ni++) {
        int col = n0 + wn * 64 + ni * 8 + 2 * q;
        float b0 = bc[col], b1 = bc[col + 1];
        #pragma unroll
        for (int mi = 0; mi < 4; mi++) {
            int row = m0 + wm * 64 + mi * 16 + g;
            float2 v0, v1;
            v0.x = gated_act(acc[mi][ni][0] + b0);
            v0.y = gated_act(acc[mi][ni][1] + b1);
            v1.x = gated_act(acc[mi][ni][2] + b0);
            v1.y = gated_act(acc[mi][ni][3] + b1);
            *(float2*)&outp[(size_t)row * DD + col]       = v0;
            *(float2*)&outp[(size_t)(row + 8) * DD + col] = v1;
        }
    }
}

extern "C" void kernel_launch(void* const* d_in, const int* in_sizes, int n_in,
                              void* d_out, int out_size)
{
    const float* inp  = (const float*)d_in[0];   // [8,1024,1024]
    const float* mem  = (const float*)d_in[1];   // [8,1024,1024]
    const float* mask = (const float*)d_in[2];   // [8,1024]
    const float* Wc   = (const float*)d_in[3];   // [1024,2048]
    const float* bc   = (const float*)d_in[4];   // [1024]
    float* outp = (float*)d_out;                 // [8,1024,1024]

    // one-time setup (first call = correctness run, NOT under graph capture)
    static cudaStream_t s2 = nullptr;
    static cudaEvent_t evFork = nullptr, evJoin = nullptr;
    if (!s2) {
        cudaStreamCreate(&s2);
        cudaEventCreateWithFlags(&evFork, cudaEventDisableTiming);
        cudaEventCreateWithFlags(&evJoin, cudaEventDisableTiming);
        cudaFuncSetAttribute(attn_kernel, cudaFuncAttributeMaxDynamicSharedMemorySize,
                             ATT_SMEM_BYTES);
        cudaFuncSetAttribute(out_gemm_kernel, cudaFuncAttributeMaxDynamicSharedMemorySize,
                             GEMM_SMEM_BYTES);
    }

    __half *xh_p, *wh_p, *memh_p;
    cudaGetSymbolAddress((void**)&xh_p, g_xh);
    cudaGetSymbolAddress((void**)&wh_p, g_wh);
    cudaGetSymbolAddress((void**)&memh_p, g_memh);

    // fork: W/X fp16 rounding on s2 (overlaps attention)
    cudaEventRecord(evFork, 0);
    cudaStreamWaitEvent(s2, evFork, 0);
    {
        int n4w = DD * 2 * DD / 4;       // 524288
        round_half_kernel<<<n4w / 256, 256, 0, s2>>>(Wc, wh_p, n4w);
        int n4x = NB * SLD * DD / 4;     // 2097152
        round_half_kernel<<<n4x / 256, 256, 0, s2>>>(inp, xh_p, n4x);
    }
    cudaEventRecord(evJoin, s2);

    // stream 0: mem -> fp16, then attention
    {
        int n4m = NB * SLM * DD / 4;     // 2097152
        round_half_kernel<<<n4m / 256, 256>>>(mem, memh_p, n4m);
    }
    dim3 agrid(SLD / BQ, HH, NB);              // 8 x 16 x 8 = 1024 blocks
    attn_kernel<<<agrid, AT, ATT_SMEM_BYTES>>>(inp, mask);

    // join, then fused projection GEMM + epilogue
    cudaStreamWaitEvent(0, evJoin, 0);
    dim3 ggrid(DD / TN2, (NB * SLD) / TM2);    // 8 x 64 = 512 blocks
    out_gemm_kernel<<<ggrid, GT2, GEMM_SMEM_BYTES>>>(bc, outp);
}